// round 9
// baseline (speedup 1.0000x reference)
#include <cuda_runtime.h>
#include <cuda_bf16.h>
#include <math.h>
#include <stdint.h>

// ---------------- problem constants ----------------
#define SS        128
#define HID       256
#define NTHREADS  512
#define KC        32               // K per weight chunk (bf16)
#define NCHUNK    28               // per MLP: layer0: 4 (Kpad=128), layers1-3: 8 each
#define ASTRIDE   264              // A plane row stride in bf16 (conflict-free ldmatrix)
#define HSTRIDE   260              // fp32 overlay row stride
#define BSTRIDE   40               // B chunk row stride in bf16 (80B, conflict-free)

// ---- shared memory byte offsets ----
#define A_HI      0                              // 128*264*2 = 67584
#define A_LO      67584                          // 67584            -> 135168
#define BUF0      135168                         // 2 bufs * 2 planes * 20480 = 81920 -> 217088
#define BPLANE    20480
#define BBUFSZ    40960
#define SM_W4     217088                         // 256*5*4 = 5120   -> 222208
#define SM_BIAS   222208                         // 256*4 = 1024     -> 223232
#define SM_OUTS   223232                         // 128*4*4 = 2048   -> 225280
#define SM_SIG    225280                         // 512
#define SM_BW     225792                         // 512
#define SM_RGB    226304                         // 1536
#define SM_Z      227840                         // 512
#define SM_WGT    228352                         // 512 -> 228864
#define SM_TOTAL  228864
// encode scratch (fp32 [128][100] = 51200B) overlays BUF0 between MLPs

// Pre-transposed bf16 hi/lo weight chunk images: [mlp][chunk][plane][256*32]
__device__ __align__(16) __nv_bfloat16 g_wimg[2][NCHUNK][2][HID * KC];

struct MLPParams { const float* W[5]; const float* b[5]; };

// ---------------- PTX helpers (all baseline sm_80 ISA) ----------------
__device__ __forceinline__ uint32_t smem_u32(const void* p) {
    uint32_t a;
    asm("{ .reg .u64 t; cvta.to.shared.u64 t, %1; cvt.u32.u64 %0, t; }" : "=r"(a) : "l"(p));
    return a;
}

#define LDSM4(r0, r1, r2, r3, addr) \
    asm volatile("ldmatrix.sync.aligned.m8n8.x4.shared.b16 {%0,%1,%2,%3}, [%4];" \
        : "=r"(r0), "=r"(r1), "=r"(r2), "=r"(r3) : "r"(addr))

#define MMA16816(c, a0, a1, a2, a3, b0, b1) \
    asm volatile("mma.sync.aligned.m16n8k16.row.col.f32.bf16.bf16.f32 " \
        "{%0,%1,%2,%3}, {%4,%5,%6,%7}, {%8,%9}, {%0,%1,%2,%3};" \
        : "+f"((c)[0]), "+f"((c)[1]), "+f"((c)[2]), "+f"((c)[3]) \
        : "r"(a0), "r"(a1), "r"(a2), "r"(a3), "r"(b0), "r"(b1))

__device__ __forceinline__ void cp16(uint32_t dst, const void* src) {
    asm volatile("cp.async.cg.shared.global [%0], [%1], 16;" :: "r"(dst), "l"(src));
}
#define CP_COMMIT() asm volatile("cp.async.commit_group;" ::: "memory")
#define CP_WAIT1()  asm volatile("cp.async.wait_group 1;" ::: "memory")
#define CP_WAIT0()  asm volatile("cp.async.wait_group 0;" ::: "memory")

__device__ __forceinline__ float sigmoidf_(float x) { return 1.0f / (1.0f + expf(-x)); }

__device__ __forceinline__ void split_pack(float v0, float v1, uint32_t& phi, uint32_t& plo) {
    __nv_bfloat16 h0 = __float2bfloat16(v0);
    __nv_bfloat16 h1 = __float2bfloat16(v1);
    __nv_bfloat16 l0 = __float2bfloat16(v0 - __bfloat162float(h0));
    __nv_bfloat16 l1 = __float2bfloat16(v1 - __bfloat162float(h1));
    phi = (uint32_t)__bfloat16_as_ushort(h0) | ((uint32_t)__bfloat16_as_ushort(h1) << 16);
    plo = (uint32_t)__bfloat16_as_ushort(l0) | ((uint32_t)__bfloat16_as_ushort(l1) << 16);
}

// ---------------- pre-pass: build [N][Kc] bf16 hi/lo chunk images ----------------
__global__ void prepass_kernel(MLPParams st, MLPParams dy) {
    const int bi  = blockIdx.x;          // 0..55
    const int mlp = bi / NCHUNK;
    const int c   = bi % NCHUNK;
    const int layer = (c < 4) ? 0 : 1 + (c - 4) / 8;
    const int kbase = (c < 4) ? c * KC : ((c - 4) % 8) * KC;
    const float* W = mlp ? dy.W[layer] : st.W[layer];
    const int Kreal = (layer == 0) ? (mlp ? 99 : 90) : HID;

    __nv_bfloat16* outH = g_wimg[mlp][c][0];
    __nv_bfloat16* outL = g_wimg[mlp][c][1];
    const int n = threadIdx.x;           // 0..255
    for (int k = 0; k < KC; k++) {
        const int kg = kbase + k;
        const float w = (kg < Kreal) ? __ldg(W + (size_t)kg * HID + n) : 0.f;
        __nv_bfloat16 h = __float2bfloat16(w);
        __nv_bfloat16 l = __float2bfloat16(w - __bfloat162float(h));
        outH[n * KC + k] = h;
        outL[n * KC + k] = l;
    }
}

// ---------------- GEMM chunk: 16 warps, warp tile 16(M) x 128(N), Kc=32 ----------------
__device__ __forceinline__ void gemm_chunk(uint32_t aHi, uint32_t aLo, uint32_t bB,
                                           float acc[16][4]) {
#pragma unroll
    for (int ks = 0; ks < 2; ks++) {
        uint32_t ah0, ah1, ah2, ah3, al0, al1, al2, al3;
        LDSM4(ah0, ah1, ah2, ah3, aHi + ks * 32);
        LDSM4(al0, al1, al2, al3, aLo + ks * 32);
        const uint32_t bk = bB + ks * 32;
#pragma unroll
        for (int p = 0; p < 8; p++) {
            uint32_t bh0, bh1, bh2, bh3, bl0, bl1, bl2, bl3;
            LDSM4(bh0, bh1, bh2, bh3, bk + p * (16 * BSTRIDE * 2));
            LDSM4(bl0, bl1, bl2, bl3, bk + BPLANE + p * (16 * BSTRIDE * 2));
            MMA16816(acc[2 * p],     ah0, ah1, ah2, ah3, bh0, bh1);
            MMA16816(acc[2 * p + 1], ah0, ah1, ah2, ah3, bh2, bh3);
            MMA16816(acc[2 * p],     ah0, ah1, ah2, ah3, bl0, bl1);
            MMA16816(acc[2 * p + 1], ah0, ah1, ah2, ah3, bl2, bl3);
            MMA16816(acc[2 * p],     al0, al1, al2, al3, bh0, bh1);
            MMA16816(acc[2 * p + 1], al0, al1, al2, al3, bh2, bh3);
        }
    }
}

// ---------------- main kernel ----------------
__global__ void __launch_bounds__(NTHREADS, 1)
nerf_main(const float* __restrict__ pts, const float* __restrict__ dir,
          const float* __restrict__ zv,  const float* __restrict__ tim,
          MLPParams st, MLPParams dy, float* __restrict__ out, int R)
{
    extern __shared__ char sm[];
    const uint32_t sbase = smem_u32(sm);

    const int tid  = threadIdx.x;
    const int wid  = tid >> 5;
    const int lane = tid & 31;
    const int ray  = blockIdx.x;

    const int mi = wid >> 1;             // 0..7  -> rows 16*mi
    const int nj = wid & 1;              // 0..1  -> cols 128*nj

    float* sZ    = (float*)(sm + SM_Z);
    float* sWgt  = (float*)(sm + SM_WGT);
    float* sSig  = (float*)(sm + SM_SIG);
    float* sBW   = (float*)(sm + SM_BW);
    float* sRgb  = (float*)(sm + SM_RGB);
    float* sOutS = (float*)(sm + SM_OUTS);
    float* sBias = (float*)(sm + SM_BIAS);
    float* sW4f  = (float*)(sm + SM_W4);
    float* sHf   = (float*)(sm + A_HI);      // fp32 overlay, stride HSTRIDE

    if (tid < SS) sZ[tid] = zv[(long)ray * SS + tid];

    // per-thread ldmatrix address components
    const int r8 = lane & 7, g = lane >> 3;
    const uint32_t aRow = (uint32_t)(16 * mi + (g & 1) * 8 + r8);
    const uint32_t aColOff = (uint32_t)((g >> 1) * 8);
    const uint32_t aHiBase = sbase + A_HI + (aRow * ASTRIDE + aColOff) * 2;
    const uint32_t aLoBase = sbase + A_LO + (aRow * ASTRIDE + aColOff) * 2;
    const uint32_t bRow = (uint32_t)(nj * 128 + (g >> 1) * 8 + r8);
    const uint32_t bOff = (bRow * BSTRIDE + (g & 1) * 8) * 2;

    const int rowTop = 16 * mi + (lane >> 2);
    const int colB   = nj * 128 + 2 * (lane & 3);

    for (int mlp = 0; mlp < 2; mlp++) {
        const float* const* Wp = mlp ? dy.W : st.W;
        const float* const* Bp = mlp ? dy.b : st.b;
        const int n4 = mlp ? 5 : 4;

        // ---- encode into fp32 scratch (overlays B buffers; all cp.async retired) ----
        CP_WAIT0();
        __syncthreads();
        float* scratch = (float*)(sm + BUF0);
        if (tid < SS) {
            const int m = tid;
            const long base = (long)ray * SS + m;
            const float p0 = pts[base*3+0], p1 = pts[base*3+1], p2 = pts[base*3+2];
            const float d0 = dir[base*3+0], d1 = dir[base*3+1], d2 = dir[base*3+2];
            const float t  = tim[base];
            float* x = scratch + m * 100;
            x[0] = p0; x[1] = p1; x[2] = p2;
            float f = 1.f; int o = 3;
#pragma unroll
            for (int l = 0; l < 10; l++) {
                float s0,c0,s1,c1,s2,c2;
                sincosf(f*p0,&s0,&c0); sincosf(f*p1,&s1,&c1); sincosf(f*p2,&s2,&c2);
                x[o]=s0; x[o+1]=s1; x[o+2]=s2; x[o+3]=c0; x[o+4]=c1; x[o+5]=c2;
                o += 6; f *= 2.f;
            }
            x[63]=d0; x[64]=d1; x[65]=d2;
            f = 1.f; o = 66;
#pragma unroll
            for (int l = 0; l < 4; l++) {
                float s0,c0,s1,c1,s2,c2;
                sincosf(f*d0,&s0,&c0); sincosf(f*d1,&s1,&c1); sincosf(f*d2,&s2,&c2);
                x[o]=s0; x[o+1]=s1; x[o+2]=s2; x[o+3]=c0; x[o+4]=c1; x[o+5]=c2;
                o += 6; f *= 2.f;
            }
            x[90]=t;
            f = 1.f; o = 91;
#pragma unroll
            for (int l = 0; l < 4; l++) {
                float s, c; sincosf(f*t, &s, &c);
                x[o]=s; x[o+1]=c; o += 2; f *= 2.f;
            }
        }
        __syncthreads();

        // ---- pack encodings to A planes (bf16 hi/lo), cols 0..127 (zero pad >=100) ----
        {
            const int m  = tid >> 2;
            const int j0 = (tid & 3) * 16;
            const float* xr = scratch + m * 100;
            uint32_t* aH = (uint32_t*)(sm + A_HI);
            uint32_t* aL = (uint32_t*)(sm + A_LO);
#pragma unroll
            for (int j = 0; j < 16; j++) {
                const int k0 = 2 * (j0 + j);
                const float v0 = (k0     < 100) ? xr[k0]     : 0.f;
                const float v1 = (k0 + 1 < 100) ? xr[k0 + 1] : 0.f;
                uint32_t phi, plo;
                split_pack(v0, v1, phi, plo);
                aH[m * (ASTRIDE/2) + j0 + j] = phi;
                aL[m * (ASTRIDE/2) + j0 + j] = plo;
            }
        }
        __syncthreads();

        // ---- prefetch chunks 0,1 ----
        int cg = 0;
        {
            for (int pc = 0; pc < 2; pc++) {
                const char* srcH = (const char*)g_wimg[mlp][pc][0];
                const char* srcL = (const char*)g_wimg[mlp][pc][1];
                const uint32_t dstB = sbase + BUF0 + pc * BBUFSZ;
#pragma unroll
                for (int i = 0; i < 2; i++) {
                    const int idx = tid + i * NTHREADS;         // 0..1023
                    const uint32_t d = dstB + (uint32_t)(idx >> 2) * (BSTRIDE*2) + (idx & 3) * 16;
                    cp16(d,          srcH + idx * 16);
                    cp16(d + BPLANE, srcL + idx * 16);
                }
                CP_COMMIT();
            }
        }

        for (int layer = 0; layer < 4; layer++) {
            // stage bias (+ final W4) for this layer
            for (int i = tid; i < HID; i += NTHREADS) sBias[i] = __ldg(Bp[layer] + i);
            if (layer == 3)
                for (int i = tid; i < HID * n4; i += NTHREADS) sW4f[i] = __ldg(Wp[4] + i);

            float acc[16][4];
#pragma unroll
            for (int a = 0; a < 16; a++)
#pragma unroll
                for (int q = 0; q < 4; q++) acc[a][q] = 0.f;

            const int nch = (layer == 0) ? 4 : 8;
            for (int c = 0; c < nch; c++) {
                CP_WAIT1();                       // chunk cg resident
                __syncthreads();
                const uint32_t bB = sbase + BUF0 + (uint32_t)(cg & 1) * BBUFSZ + bOff;
                gemm_chunk(aHiBase + c * (KC * 2), aLoBase + c * (KC * 2), bB, acc);
                __syncthreads();
                // prefetch chunk cg+2 into buf (cg&1); always commit to keep group count uniform
                if (cg + 2 < NCHUNK) {
                    const int nc = cg + 2;
                    const char* srcH = (const char*)g_wimg[mlp][nc][0];
                    const char* srcL = (const char*)g_wimg[mlp][nc][1];
                    const uint32_t dstB = sbase + BUF0 + (uint32_t)(cg & 1) * BBUFSZ;
#pragma unroll
                    for (int i = 0; i < 2; i++) {
                        const int idx = tid + i * NTHREADS;
                        const uint32_t d = dstB + (uint32_t)(idx >> 2) * (BSTRIDE*2) + (idx & 3) * 16;
                        cp16(d,          srcH + idx * 16);
                        cp16(d + BPLANE, srcL + idx * 16);
                    }
                }
                CP_COMMIT();
                cg++;
            }

            // ---- epilogue ----
            if (layer < 3) {
                uint32_t* aH = (uint32_t*)(sm + A_HI);
                uint32_t* aL = (uint32_t*)(sm + A_LO);
#pragma unroll
                for (int nb = 0; nb < 16; nb++) {
                    const int col = colB + nb * 8;
                    const float b0 = sBias[col], b1 = sBias[col + 1];
                    const float h00 = fmaxf(acc[nb][0] + b0, 0.f);
                    const float h01 = fmaxf(acc[nb][1] + b1, 0.f);
                    const float h10 = fmaxf(acc[nb][2] + b0, 0.f);
                    const float h11 = fmaxf(acc[nb][3] + b1, 0.f);
                    uint32_t phi, plo;
                    split_pack(h00, h01, phi, plo);
                    aH[rowTop * (ASTRIDE/2) + (col >> 1)] = phi;
                    aL[rowTop * (ASTRIDE/2) + (col >> 1)] = plo;
                    split_pack(h10, h11, phi, plo);
                    aH[(rowTop + 8) * (ASTRIDE/2) + (col >> 1)] = phi;
                    aL[(rowTop + 8) * (ASTRIDE/2) + (col >> 1)] = plo;
                }
            } else {
                // fp32 relu output into overlay (A planes fully consumed)
#pragma unroll
                for (int nb = 0; nb < 16; nb++) {
                    const int col = colB + nb * 8;
                    const float b0 = sBias[col], b1 = sBias[col + 1];
                    sHf[rowTop * HSTRIDE + col]           = fmaxf(acc[nb][0] + b0, 0.f);
                    sHf[rowTop * HSTRIDE + col + 1]       = fmaxf(acc[nb][1] + b1, 0.f);
                    sHf[(rowTop + 8) * HSTRIDE + col]     = fmaxf(acc[nb][2] + b0, 0.f);
                    sHf[(rowTop + 8) * HSTRIDE + col + 1] = fmaxf(acc[nb][3] + b1, 0.f);
                }
            }
            __syncthreads();
        }

        // ---- final 256 -> n4 dot per sample ----
        if (tid < SS) {
            float o5[5];
            const float* b4 = Bp[4];
#pragma unroll
            for (int j = 0; j < 5; j++) o5[j] = (j < n4) ? __ldg(b4 + j) : 0.f;
            const float* arow = sHf + tid * HSTRIDE;
            for (int k = 0; k < HID; k += 4) {
                const float4 a = *reinterpret_cast<const float4*>(arow + k);
#pragma unroll
                for (int kk = 0; kk < 4; kk++) {
                    const float av = (kk == 0) ? a.x : (kk == 1) ? a.y : (kk == 2) ? a.z : a.w;
#pragma unroll
                    for (int j = 0; j < 5; j++)
                        if (j < n4) o5[j] += av * sW4f[(k + kk) * n4 + j];
                }
            }
            const int m = tid;
            if (mlp == 0) {
                sOutS[m*4+0] = o5[0]; sOutS[m*4+1] = o5[1];
                sOutS[m*4+2] = o5[2]; sOutS[m*4+3] = o5[3];
            } else {
                const float bw = sigmoidf_(o5[4]);
                sSig[m] = (1.f - bw) * sOutS[m*4+0] + bw * o5[0];
                sBW[m]  = bw;
#pragma unroll
                for (int cc = 0; cc < 3; cc++) {
                    const float rs = sigmoidf_(sOutS[m*4+1+cc]);
                    const float rd = sigmoidf_(o5[1+cc]);
                    sRgb[m*3+cc] = (1.f - bw) * rs + bw * rd;
                }
            }
        }
        __syncthreads();
    }

    // ---- transmittance scan + ray reductions ----
    if (tid == 0) {
        float T = 1.f, r0 = 0.f, r1 = 0.f, r2 = 0.f, dep = 0.f;
        for (int m = 0; m < SS; m++) {
            const float z = sZ[m];
            const float delta = (m < SS - 1) ? (sZ[m + 1] - z) : 1e10f;
            const float alpha = 1.f - expf(-sSig[m] * delta);
            const float w = alpha * T;
            T *= (1.f - alpha + 1e-10f);
            sWgt[m] = w;
            r0 += w * sRgb[m*3+0];
            r1 += w * sRgb[m*3+1];
            r2 += w * sRgb[m*3+2];
            dep += w * z;
        }
        out[ray*3+0] = r0; out[ray*3+1] = r1; out[ray*3+2] = r2;
        out[(long)R * 3 + ray] = dep;
    }
    __syncthreads();

    if (tid < SS) {
        const int m = tid;
        const float w  = sWgt[m];
        const float bw = sBW[m];
        const long o = (long)ray * SS + m;
        const long base = (long)R * 4;
        const long rs = (long)R * SS;
        out[base + o]          = w;
        out[base + rs + o]     = (1.f - bw) * w;
        out[base + 2 * rs + o] = bw * w;
    }
}

extern "C" void kernel_launch(void* const* d_in, const int* in_sizes, int n_in,
                              void* d_out, int out_size)
{
    const float* pts = (const float*)d_in[0];
    const float* dir = (const float*)d_in[1];
    const float* zv  = (const float*)d_in[2];
    const float* tim = (const float*)d_in[3];

    MLPParams st, dy;
    for (int i = 0; i < 5; i++) {
        st.W[i] = (const float*)d_in[4 + 4 * i];
        st.b[i] = (const float*)d_in[5 + 4 * i];
        dy.W[i] = (const float*)d_in[6 + 4 * i];
        dy.b[i] = (const float*)d_in[7 + 4 * i];
    }

    const int R = in_sizes[2] / SS;

    prepass_kernel<<<2 * NCHUNK, 256>>>(st, dy);

    cudaFuncSetAttribute(nerf_main, cudaFuncAttributeMaxDynamicSharedMemorySize, SM_TOTAL);
    nerf_main<<<R, NTHREADS, SM_TOTAL>>>(pts, dir, zv, tim, st, dy, (float*)d_out, R);
}

// round 10
// speedup vs baseline: 1.0957x; 1.0957x over previous
#include <cuda_runtime.h>
#include <cuda_bf16.h>
#include <math.h>
#include <stdint.h>

// ---------------- problem constants ----------------
#define SS        128
#define HID       256
#define NTHREADS  512
#define KC        32               // K per weight chunk (bf16)
#define NCHUNK    28               // per MLP: layer0: 4 (Kpad=128), layers1-3: 8 each
#define ASTRIDE   264              // A plane row stride in bf16 (33*16B rows: conflict-free ldmatrix)
#define HSTRIDE   260              // fp32 overlay row stride
#define BSTRIDE   40               // B chunk row stride in bf16 (5*16B rows: conflict-free)

// ---- shared memory byte offsets ----
#define A_HI      0                              // 128*264*2 = 67584
#define A_LO      67584                          // 67584            -> 135168
#define BUF0      135168                         // 2 bufs * 2 planes * 20480 = 81920 -> 217088
#define BPLANE    20480
#define BBUFSZ    40960
#define SM_W4     217088                         // 256*5*4 = 5120   -> 222208
#define SM_BIAS   222208                         // 256*4 = 1024     -> 223232
#define SM_OUTS   223232                         // 128*4*4 = 2048   -> 225280  (reused as alpha/oma)
#define SM_SIG    225280                         // 512
#define SM_BW     225792                         // 512
#define SM_RGB    226304                         // 1536
#define SM_Z      227840                         // 512
#define SM_WGT    228352                         // 512 -> 228864
#define SM_TOTAL  228864
// encode scratch (fp32 [128][100] = 51200B) overlays BUF0 between MLPs

// Pre-transposed bf16 hi/lo weight chunk images: [mlp][chunk][plane][256*32]
__device__ __align__(16) __nv_bfloat16 g_wimg[2][NCHUNK][2][HID * KC];

struct MLPParams { const float* W[5]; const float* b[5]; };

// ---------------- PTX helpers (all baseline sm_80 ISA) ----------------
__device__ __forceinline__ uint32_t smem_u32(const void* p) {
    uint32_t a;
    asm("{ .reg .u64 t; cvta.to.shared.u64 t, %1; cvt.u32.u64 %0, t; }" : "=r"(a) : "l"(p));
    return a;
}

#define LDSM4(r0, r1, r2, r3, addr) \
    asm volatile("ldmatrix.sync.aligned.m8n8.x4.shared.b16 {%0,%1,%2,%3}, [%4];" \
        : "=r"(r0), "=r"(r1), "=r"(r2), "=r"(r3) : "r"(addr))

#define MMA16816(c, a0, a1, a2, a3, b0, b1) \
    asm volatile("mma.sync.aligned.m16n8k16.row.col.f32.bf16.bf16.f32 " \
        "{%0,%1,%2,%3}, {%4,%5,%6,%7}, {%8,%9}, {%0,%1,%2,%3};" \
        : "+f"((c)[0]), "+f"((c)[1]), "+f"((c)[2]), "+f"((c)[3]) \
        : "r"(a0), "r"(a1), "r"(a2), "r"(a3), "r"(b0), "r"(b1))

__device__ __forceinline__ void cp16(uint32_t dst, const void* src) {
    asm volatile("cp.async.cg.shared.global [%0], [%1], 16;" :: "r"(dst), "l"(src));
}
#define CP_COMMIT() asm volatile("cp.async.commit_group;" ::: "memory")
#define CP_WAIT1()  asm volatile("cp.async.wait_group 1;" ::: "memory")
#define CP_WAIT0()  asm volatile("cp.async.wait_group 0;" ::: "memory")

__device__ __forceinline__ float sigmoidf_(float x) { return 1.0f / (1.0f + expf(-x)); }

__device__ __forceinline__ void split_pack(float v0, float v1, uint32_t& phi, uint32_t& plo) {
    __nv_bfloat16 h0 = __float2bfloat16(v0);
    __nv_bfloat16 h1 = __float2bfloat16(v1);
    __nv_bfloat16 l0 = __float2bfloat16(v0 - __bfloat162float(h0));
    __nv_bfloat16 l1 = __float2bfloat16(v1 - __bfloat162float(h1));
    phi = (uint32_t)__bfloat16_as_ushort(h0) | ((uint32_t)__bfloat16_as_ushort(h1) << 16);
    plo = (uint32_t)__bfloat16_as_ushort(l0) | ((uint32_t)__bfloat16_as_ushort(l1) << 16);
}

// ---------------- pre-pass: build [N][Kc] bf16 hi/lo chunk images ----------------
__global__ void prepass_kernel(MLPParams st, MLPParams dy) {
    const int bi  = blockIdx.x;          // 0..55
    const int mlp = bi / NCHUNK;
    const int c   = bi % NCHUNK;
    const int layer = (c < 4) ? 0 : 1 + (c - 4) / 8;
    const int kbase = (c < 4) ? c * KC : ((c - 4) % 8) * KC;
    const float* W = mlp ? dy.W[layer] : st.W[layer];
    const int Kreal = (layer == 0) ? (mlp ? 99 : 90) : HID;

    __nv_bfloat16* outH = g_wimg[mlp][c][0];
    __nv_bfloat16* outL = g_wimg[mlp][c][1];
    const int n = threadIdx.x;           // 0..255
    for (int k = 0; k < KC; k++) {
        const int kg = kbase + k;
        const float w = (kg < Kreal) ? __ldg(W + (size_t)kg * HID + n) : 0.f;
        __nv_bfloat16 h = __float2bfloat16(w);
        __nv_bfloat16 l = __float2bfloat16(w - __bfloat162float(h));
        outH[n * KC + k] = h;
        outL[n * KC + k] = l;
    }
}

// ---------------- GEMM chunk: 16 warps in 4(M)x4(N), warp tile 32x64, Kc=32 ----------------
// acc index: mb*8 + nf  (mb 0..1 = 16-row block, nf 0..7 = n8 fragment)
__device__ __forceinline__ void gemm_chunk(uint32_t aHi, uint32_t aLo, uint32_t bB,
                                           float acc[16][4]) {
#pragma unroll
    for (int ks = 0; ks < 2; ks++) {
        uint32_t ah[2][4], al[2][4];
        LDSM4(ah[0][0], ah[0][1], ah[0][2], ah[0][3], aHi + ks * 32);
        LDSM4(ah[1][0], ah[1][1], ah[1][2], ah[1][3], aHi + 16 * (ASTRIDE * 2) + ks * 32);
        LDSM4(al[0][0], al[0][1], al[0][2], al[0][3], aLo + ks * 32);
        LDSM4(al[1][0], al[1][1], al[1][2], al[1][3], aLo + 16 * (ASTRIDE * 2) + ks * 32);
        const uint32_t bk = bB + ks * 32;
#pragma unroll
        for (int nb = 0; nb < 4; nb++) {
            uint32_t bh0, bh1, bh2, bh3, bl0, bl1, bl2, bl3;
            LDSM4(bh0, bh1, bh2, bh3, bk + nb * (16 * BSTRIDE * 2));
            LDSM4(bl0, bl1, bl2, bl3, bk + BPLANE + nb * (16 * BSTRIDE * 2));
#pragma unroll
            for (int mb = 0; mb < 2; mb++) {
                float* c0 = acc[mb * 8 + 2 * nb];
                float* c1 = acc[mb * 8 + 2 * nb + 1];
                MMA16816(c0, ah[mb][0], ah[mb][1], ah[mb][2], ah[mb][3], bh0, bh1);
                MMA16816(c1, ah[mb][0], ah[mb][1], ah[mb][2], ah[mb][3], bh2, bh3);
                MMA16816(c0, ah[mb][0], ah[mb][1], ah[mb][2], ah[mb][3], bl0, bl1);
                MMA16816(c1, ah[mb][0], ah[mb][1], ah[mb][2], ah[mb][3], bl2, bl3);
                MMA16816(c0, al[mb][0], al[mb][1], al[mb][2], al[mb][3], bh0, bh1);
                MMA16816(c1, al[mb][0], al[mb][1], al[mb][2], al[mb][3], bh2, bh3);
            }
        }
    }
}

// ---------------- main kernel ----------------
__global__ void __launch_bounds__(NTHREADS, 1)
nerf_main(const float* __restrict__ pts, const float* __restrict__ dir,
          const float* __restrict__ zv,  const float* __restrict__ tim,
          MLPParams st, MLPParams dy, float* __restrict__ out, int R)
{
    extern __shared__ char sm[];
    const uint32_t sbase = smem_u32(sm);

    const int tid  = threadIdx.x;
    const int wid  = tid >> 5;
    const int lane = tid & 31;
    const int ray  = blockIdx.x;

    const int mi = wid >> 2;             // 0..3  -> rows 32*mi
    const int nj = wid & 3;              // 0..3  -> cols 64*nj

    float* sZ    = (float*)(sm + SM_Z);
    float* sWgt  = (float*)(sm + SM_WGT);
    float* sSig  = (float*)(sm + SM_SIG);
    float* sBW   = (float*)(sm + SM_BW);
    float* sRgb  = (float*)(sm + SM_RGB);
    float* sOutS = (float*)(sm + SM_OUTS);
    float* sBias = (float*)(sm + SM_BIAS);
    float* sW4f  = (float*)(sm + SM_W4);
    float* sHf   = (float*)(sm + A_HI);      // fp32 overlay, stride HSTRIDE

    if (tid < SS) sZ[tid] = zv[(long)ray * SS + tid];

    // per-thread ldmatrix address components
    const int r8 = lane & 7, g = lane >> 3;
    const uint32_t aRow = (uint32_t)(32 * mi + (g & 1) * 8 + r8);
    const uint32_t aColOff = (uint32_t)((g >> 1) * 8);
    const uint32_t aHiBase = sbase + A_HI + (aRow * ASTRIDE + aColOff) * 2;
    const uint32_t aLoBase = sbase + A_LO + (aRow * ASTRIDE + aColOff) * 2;
    const uint32_t bRow = (uint32_t)(nj * 64 + (g >> 1) * 8 + r8);
    const uint32_t bOff = (bRow * BSTRIDE + (g & 1) * 8) * 2;

    const int rowBase = 32 * mi + (lane >> 2);     // + 16*mb, +8 for c[2..3]
    const int colBase = nj * 64 + 2 * (lane & 3);  // + 8*nf

    for (int mlp = 0; mlp < 2; mlp++) {
        const float* const* Wp = mlp ? dy.W : st.W;
        const float* const* Bp = mlp ? dy.b : st.b;
        const int n4 = mlp ? 5 : 4;

        // ---- encode into fp32 scratch (overlays B buffers; all cp.async retired) ----
        CP_WAIT0();
        __syncthreads();
        float* scratch = (float*)(sm + BUF0);
        if (tid < SS) {
            const int m = tid;
            const long base = (long)ray * SS + m;
            const float p0 = pts[base*3+0], p1 = pts[base*3+1], p2 = pts[base*3+2];
            const float d0 = dir[base*3+0], d1 = dir[base*3+1], d2 = dir[base*3+2];
            const float t  = tim[base];
            float* x = scratch + m * 100;
            x[0] = p0; x[1] = p1; x[2] = p2;
            float f = 1.f; int o = 3;
#pragma unroll
            for (int l = 0; l < 10; l++) {
                float s0,c0,s1,c1,s2,c2;
                sincosf(f*p0,&s0,&c0); sincosf(f*p1,&s1,&c1); sincosf(f*p2,&s2,&c2);
                x[o]=s0; x[o+1]=s1; x[o+2]=s2; x[o+3]=c0; x[o+4]=c1; x[o+5]=c2;
                o += 6; f *= 2.f;
            }
            x[63]=d0; x[64]=d1; x[65]=d2;
            f = 1.f; o = 66;
#pragma unroll
            for (int l = 0; l < 4; l++) {
                float s0,c0,s1,c1,s2,c2;
                sincosf(f*d0,&s0,&c0); sincosf(f*d1,&s1,&c1); sincosf(f*d2,&s2,&c2);
                x[o]=s0; x[o+1]=s1; x[o+2]=s2; x[o+3]=c0; x[o+4]=c1; x[o+5]=c2;
                o += 6; f *= 2.f;
            }
            x[90]=t;
            f = 1.f; o = 91;
#pragma unroll
            for (int l = 0; l < 4; l++) {
                float s, c; sincosf(f*t, &s, &c);
                x[o]=s; x[o+1]=c; o += 2; f *= 2.f;
            }
        }
        __syncthreads();

        // ---- pack encodings to A planes (bf16 hi/lo), cols 0..127 (zero pad >=100) ----
        {
            const int m  = tid >> 2;
            const int j0 = (tid & 3) * 16;
            const float* xr = scratch + m * 100;
            uint32_t* aH = (uint32_t*)(sm + A_HI);
            uint32_t* aL = (uint32_t*)(sm + A_LO);
#pragma unroll
            for (int j = 0; j < 16; j++) {
                const int k0 = 2 * (j0 + j);
                const float v0 = (k0     < 100) ? xr[k0]     : 0.f;
                const float v1 = (k0 + 1 < 100) ? xr[k0 + 1] : 0.f;
                uint32_t phi, plo;
                split_pack(v0, v1, phi, plo);
                aH[m * (ASTRIDE/2) + j0 + j] = phi;
                aL[m * (ASTRIDE/2) + j0 + j] = plo;
            }
        }
        __syncthreads();

        // ---- prefetch chunks 0,1 ----
        int cg = 0;
        {
            for (int pc = 0; pc < 2; pc++) {
                const char* srcH = (const char*)g_wimg[mlp][pc][0];
                const char* srcL = (const char*)g_wimg[mlp][pc][1];
                const uint32_t dstB = sbase + BUF0 + pc * BBUFSZ;
#pragma unroll
                for (int i = 0; i < 2; i++) {
                    const int idx = tid + i * NTHREADS;         // 0..1023
                    const uint32_t d = dstB + (uint32_t)(idx >> 2) * (BSTRIDE*2) + (idx & 3) * 16;
                    cp16(d,          srcH + idx * 16);
                    cp16(d + BPLANE, srcL + idx * 16);
                }
                CP_COMMIT();
            }
        }

        for (int layer = 0; layer < 4; layer++) {
            // stage bias (+ final W4) for this layer (overlaps chunk-0 wait)
            for (int i = tid; i < HID; i += NTHREADS) sBias[i] = __ldg(Bp[layer] + i);
            if (layer == 3)
                for (int i = tid; i < HID * n4; i += NTHREADS) sW4f[i] = __ldg(Wp[4] + i);

            float acc[16][4];
#pragma unroll
            for (int a = 0; a < 16; a++)
#pragma unroll
                for (int q = 0; q < 4; q++) acc[a][q] = 0.f;

            const int nch = (layer == 0) ? 4 : 8;
            for (int c = 0; c < nch; c++) {
                CP_WAIT1();                       // chunk cg resident
                __syncthreads();
                const uint32_t bB = sbase + BUF0 + (uint32_t)(cg & 1) * BBUFSZ + bOff;
                gemm_chunk(aHiBase + c * (KC * 2), aLoBase + c * (KC * 2), bB, acc);
                __syncthreads();
                // prefetch chunk cg+2 into buf (cg&1); always commit to keep group count uniform
                if (cg + 2 < NCHUNK) {
                    const int nc = cg + 2;
                    const char* srcH = (const char*)g_wimg[mlp][nc][0];
                    const char* srcL = (const char*)g_wimg[mlp][nc][1];
                    const uint32_t dstB = sbase + BUF0 + (uint32_t)(cg & 1) * BBUFSZ;
#pragma unroll
                    for (int i = 0; i < 2; i++) {
                        const int idx = tid + i * NTHREADS;
                        const uint32_t d = dstB + (uint32_t)(idx >> 2) * (BSTRIDE*2) + (idx & 3) * 16;
                        cp16(d,          srcH + idx * 16);
                        cp16(d + BPLANE, srcL + idx * 16);
                    }
                }
                CP_COMMIT();
                cg++;
            }

            // ---- epilogue ----
            if (layer < 3) {
                uint32_t* aH = (uint32_t*)(sm + A_HI);
                uint32_t* aL = (uint32_t*)(sm + A_LO);
#pragma unroll
                for (int idx = 0; idx < 16; idx++) {
                    const int mb = idx >> 3, nf = idx & 7;
                    const int row = rowBase + 16 * mb;
                    const int col = colBase + 8 * nf;
                    const float b0 = sBias[col], b1 = sBias[col + 1];
                    const float h00 = fmaxf(acc[idx][0] + b0, 0.f);
                    const float h01 = fmaxf(acc[idx][1] + b1, 0.f);
                    const float h10 = fmaxf(acc[idx][2] + b0, 0.f);
                    const float h11 = fmaxf(acc[idx][3] + b1, 0.f);
                    uint32_t phi, plo;
                    split_pack(h00, h01, phi, plo);
                    aH[row * (ASTRIDE/2) + (col >> 1)] = phi;
                    aL[row * (ASTRIDE/2) + (col >> 1)] = plo;
                    split_pack(h10, h11, phi, plo);
                    aH[(row + 8) * (ASTRIDE/2) + (col >> 1)] = phi;
                    aL[(row + 8) * (ASTRIDE/2) + (col >> 1)] = plo;
                }
            } else {
                // fp32 relu output into overlay (A planes fully consumed)
#pragma unroll
                for (int idx = 0; idx < 16; idx++) {
                    const int mb = idx >> 3, nf = idx & 7;
                    const int row = rowBase + 16 * mb;
                    const int col = colBase + 8 * nf;
                    const float b0 = sBias[col], b1 = sBias[col + 1];
                    sHf[row * HSTRIDE + col]           = fmaxf(acc[idx][0] + b0, 0.f);
                    sHf[row * HSTRIDE + col + 1]       = fmaxf(acc[idx][1] + b1, 0.f);
                    sHf[(row + 8) * HSTRIDE + col]     = fmaxf(acc[idx][2] + b0, 0.f);
                    sHf[(row + 8) * HSTRIDE + col + 1] = fmaxf(acc[idx][3] + b1, 0.f);
                }
            }
            __syncthreads();
        }

        // ---- final 256 -> n4 dot per sample ----
        if (tid < SS) {
            float o5[5];
            const float* b4 = Bp[4];
#pragma unroll
            for (int j = 0; j < 5; j++) o5[j] = (j < n4) ? __ldg(b4 + j) : 0.f;
            const float* arow = sHf + tid * HSTRIDE;
            for (int k = 0; k < HID; k += 4) {
                const float4 a = *reinterpret_cast<const float4*>(arow + k);
#pragma unroll
                for (int kk = 0; kk < 4; kk++) {
                    const float av = (kk == 0) ? a.x : (kk == 1) ? a.y : (kk == 2) ? a.z : a.w;
#pragma unroll
                    for (int j = 0; j < 5; j++)
                        if (j < n4) o5[j] += av * sW4f[(k + kk) * n4 + j];
                }
            }
            const int m = tid;
            if (mlp == 0) {
                sOutS[m*4+0] = o5[0]; sOutS[m*4+1] = o5[1];
                sOutS[m*4+2] = o5[2]; sOutS[m*4+3] = o5[3];
            } else {
                const float bw = sigmoidf_(o5[4]);
                sSig[m] = (1.f - bw) * sOutS[m*4+0] + bw * o5[0];
                sBW[m]  = bw;
#pragma unroll
                for (int cc = 0; cc < 3; cc++) {
                    const float rs = sigmoidf_(sOutS[m*4+1+cc]);
                    const float rd = sigmoidf_(o5[1+cc]);
                    sRgb[m*3+cc] = (1.f - bw) * rs + bw * rd;
                }
            }
        }
        __syncthreads();
    }

    // ---- parallel alpha, then warp-0 prefix-product scan + reductions ----
    float* sAlpha = sOutS;            // reuse (sOutS dead now)
    float* sOma   = sOutS + SS;
    if (tid < SS) {
        const float z = sZ[tid];
        const float delta = (tid < SS - 1) ? (sZ[tid + 1] - z) : 1e10f;
        const float alpha = 1.f - expf(-sSig[tid] * delta);
        sAlpha[tid] = alpha;
        sOma[tid]   = 1.f - alpha + 1e-10f;
    }
    __syncthreads();
    if (wid == 0) {
        float a[4], o[4], zr[4], rg[4][3];
#pragma unroll
        for (int j = 0; j < 4; j++) {
            const int m = 4 * lane + j;
            a[j] = sAlpha[m]; o[j] = sOma[m]; zr[j] = sZ[m];
            rg[j][0] = sRgb[m*3+0]; rg[j][1] = sRgb[m*3+1]; rg[j][2] = sRgb[m*3+2];
        }
        float run = o[0] * o[1] * o[2] * o[3];
#pragma unroll
        for (int d = 1; d < 32; d <<= 1) {
            const float v = __shfl_up_sync(0xffffffffu, run, d);
            if (lane >= d) run *= v;
        }
        float T = __shfl_up_sync(0xffffffffu, run, 1);
        if (lane == 0) T = 1.f;
        float r0 = 0.f, r1 = 0.f, r2 = 0.f, dep = 0.f;
#pragma unroll
        for (int j = 0; j < 4; j++) {
            const float w = a[j] * T;
            sWgt[4 * lane + j] = w;
            r0 += w * rg[j][0]; r1 += w * rg[j][1]; r2 += w * rg[j][2];
            dep += w * zr[j];
            T *= o[j];
        }
#pragma unroll
        for (int d = 16; d > 0; d >>= 1) {
            r0  += __shfl_xor_sync(0xffffffffu, r0, d);
            r1  += __shfl_xor_sync(0xffffffffu, r1, d);
            r2  += __shfl_xor_sync(0xffffffffu, r2, d);
            dep += __shfl_xor_sync(0xffffffffu, dep, d);
        }
        if (lane == 0) {
            out[ray*3+0] = r0; out[ray*3+1] = r1; out[ray*3+2] = r2;
            out[(long)R * 3 + ray] = dep;
        }
    }
    __syncthreads();

    if (tid < SS) {
        const int m = tid;
        const float w  = sWgt[m];
        const float bw = sBW[m];
        const long o = (long)ray * SS + m;
        const long base = (long)R * 4;
        const long rs = (long)R * SS;
        out[base + o]          = w;
        out[base + rs + o]     = (1.f - bw) * w;
        out[base + 2 * rs + o] = bw * w;
    }
}

extern "C" void kernel_launch(void* const* d_in, const int* in_sizes, int n_in,
                              void* d_out, int out_size)
{
    const float* pts = (const float*)d_in[0];
    const float* dir = (const float*)d_in[1];
    const float* zv  = (const float*)d_in[2];
    const float* tim = (const float*)d_in[3];

    MLPParams st, dy;
    for (int i = 0; i < 5; i++) {
        st.W[i] = (const float*)d_in[4 + 4 * i];
        st.b[i] = (const float*)d_in[5 + 4 * i];
        dy.W[i] = (const float*)d_in[6 + 4 * i];
        dy.b[i] = (const float*)d_in[7 + 4 * i];
    }

    const int R = in_sizes[2] / SS;

    prepass_kernel<<<2 * NCHUNK, 256>>>(st, dy);

    cudaFuncSetAttribute(nerf_main, cudaFuncAttributeMaxDynamicSharedMemorySize, SM_TOTAL);
    nerf_main<<<R, NTHREADS, SM_TOTAL>>>(pts, dir, zv, tim, st, dy, (float*)d_out, R);
}

// round 11
// speedup vs baseline: 1.4237x; 1.2993x over previous
#include <cuda_runtime.h>
#include <cuda_fp16.h>
#include <math.h>
#include <stdint.h>

// ---------------- problem constants ----------------
#define SS        128
#define HID       256
#define NTHREADS  512
#define KC        64               // K per weight chunk (fp16)
#define NCHUNK    14               // per MLP: layer0: 2 (Kpad=128), layers1-3: 4 each
#define ASTRIDE   264              // A plane row stride in fp16 (33*16B: conflict-free ldmatrix)
#define HSTRIDE   260              // fp32 overlay row stride
#define BSTRIDE   72               // B chunk row stride in fp16 (9*16B: 9 mod 8 = 1, conflict-free)

// ---- shared memory byte offsets ----
#define A_HI      0                              // 128*264*2 = 67584
#define BUF0      67584                          // 2 bufs * 73728 = 147456 -> 215040
#define BPLANE    36864                          // 256*72*2
#define BBUFSZ    73728                          // hi + lo plane
#define SM_W4     215040                         // 256*5*4 = 5120   -> 220160
#define SM_BIAS   220160                         // 256*4 = 1024     -> 221184
#define SM_OUTS   221184                         // 128*4*4 = 2048   -> 223232 (reused as alpha/oma)
#define SM_SIG    223232                         // 512
#define SM_BW     223744                         // 512
#define SM_RGB    224256                         // 1536
#define SM_Z      225792                         // 512
#define SM_WGT    226304                         // 512 -> 226816
#define SM_TOTAL  226816
// encode scratch (fp32 [128][100] = 51200B) and layer-3 fp32 overlay (133120B) overlay BUF0

// Pre-transposed fp16 hi/lo weight chunk images: [mlp][chunk][plane][256*64]
__device__ __align__(16) __half g_wimg[2][NCHUNK][2][HID * KC];

struct MLPParams { const float* W[5]; const float* b[5]; };

// ---------------- PTX helpers (all baseline sm_80 ISA) ----------------
__device__ __forceinline__ uint32_t smem_u32(const void* p) {
    uint32_t a;
    asm("{ .reg .u64 t; cvta.to.shared.u64 t, %1; cvt.u32.u64 %0, t; }" : "=r"(a) : "l"(p));
    return a;
}

#define LDSM4(r0, r1, r2, r3, addr) \
    asm volatile("ldmatrix.sync.aligned.m8n8.x4.shared.b16 {%0,%1,%2,%3}, [%4];" \
        : "=r"(r0), "=r"(r1), "=r"(r2), "=r"(r3) : "r"(addr))

#define MMA16816(c, a0, a1, a2, a3, b0, b1) \
    asm volatile("mma.sync.aligned.m16n8k16.row.col.f32.f16.f16.f32 " \
        "{%0,%1,%2,%3}, {%4,%5,%6,%7}, {%8,%9}, {%0,%1,%2,%3};" \
        : "+f"((c)[0]), "+f"((c)[1]), "+f"((c)[2]), "+f"((c)[3]) \
        : "r"(a0), "r"(a1), "r"(a2), "r"(a3), "r"(b0), "r"(b1))

__device__ __forceinline__ void cp16(uint32_t dst, const void* src) {
    asm volatile("cp.async.cg.shared.global [%0], [%1], 16;" :: "r"(dst), "l"(src));
}
#define CP_COMMIT() asm volatile("cp.async.commit_group;" ::: "memory")
#define CP_WAIT1()  asm volatile("cp.async.wait_group 1;" ::: "memory")
#define CP_WAIT0()  asm volatile("cp.async.wait_group 0;" ::: "memory")

__device__ __forceinline__ float sigmoidf_(float x) { return 1.0f / (1.0f + expf(-x)); }

__device__ __forceinline__ uint32_t pack_h2(float v0, float v1) {
    __half2 h = __floats2half2_rn(v0, v1);          // low = v0 (first in memory)
    return *reinterpret_cast<uint32_t*>(&h);
}

// ---------------- pre-pass: build [N][Kc] fp16 hi/lo chunk images ----------------
__global__ void prepass_kernel(MLPParams st, MLPParams dy) {
    const int bi  = blockIdx.x;          // 0..27
    const int mlp = bi / NCHUNK;
    const int c   = bi % NCHUNK;
    const int layer = (c < 2) ? 0 : 1 + (c - 2) / 4;
    const int kbase = (c < 2) ? c * KC : ((c - 2) % 4) * KC;
    const float* W = mlp ? dy.W[layer] : st.W[layer];
    const int Kreal = (layer == 0) ? (mlp ? 99 : 90) : HID;

    __half* outH = g_wimg[mlp][c][0];
    __half* outL = g_wimg[mlp][c][1];
    const int n = threadIdx.x;           // 0..255
    for (int k = 0; k < KC; k++) {
        const int kg = kbase + k;
        const float w = (kg < Kreal) ? __ldg(W + (size_t)kg * HID + n) : 0.f;
        __half h = __float2half_rn(w);
        __half l = __float2half_rn(w - __half2float(h));
        outH[n * KC + k] = h;
        outL[n * KC + k] = l;
    }
}

// ---------------- GEMM chunk: 16 warps in 4(M)x4(N), warp tile 32x64, Kc=64 ----------------
// acc index: mb*8 + nf  (mb 0..1 = 16-row block, nf 0..7 = n8 fragment)
__device__ __forceinline__ void gemm_chunk(uint32_t aBase, uint32_t bB, float acc[16][4]) {
#pragma unroll
    for (int ks = 0; ks < 4; ks++) {
        uint32_t ah[2][4];
        LDSM4(ah[0][0], ah[0][1], ah[0][2], ah[0][3], aBase + ks * 32);
        LDSM4(ah[1][0], ah[1][1], ah[1][2], ah[1][3], aBase + 16 * (ASTRIDE * 2) + ks * 32);
        const uint32_t bk = bB + ks * 32;
#pragma unroll
        for (int nb = 0; nb < 4; nb++) {
            uint32_t bh0, bh1, bh2, bh3, bl0, bl1, bl2, bl3;
            LDSM4(bh0, bh1, bh2, bh3, bk + nb * (16 * BSTRIDE * 2));
            LDSM4(bl0, bl1, bl2, bl3, bk + BPLANE + nb * (16 * BSTRIDE * 2));
#pragma unroll
            for (int mb = 0; mb < 2; mb++) {
                float* c0 = acc[mb * 8 + 2 * nb];
                float* c1 = acc[mb * 8 + 2 * nb + 1];
                MMA16816(c0, ah[mb][0], ah[mb][1], ah[mb][2], ah[mb][3], bh0, bh1);
                MMA16816(c1, ah[mb][0], ah[mb][1], ah[mb][2], ah[mb][3], bh2, bh3);
                MMA16816(c0, ah[mb][0], ah[mb][1], ah[mb][2], ah[mb][3], bl0, bl1);
                MMA16816(c1, ah[mb][0], ah[mb][1], ah[mb][2], ah[mb][3], bl2, bl3);
            }
        }
    }
}

// ---------------- main kernel ----------------
__global__ void __launch_bounds__(NTHREADS, 1)
nerf_main(const float* __restrict__ pts, const float* __restrict__ dir,
          const float* __restrict__ zv,  const float* __restrict__ tim,
          MLPParams st, MLPParams dy, float* __restrict__ out, int R)
{
    extern __shared__ char sm[];
    const uint32_t sbase = smem_u32(sm);

    const int tid  = threadIdx.x;
    const int wid  = tid >> 5;
    const int lane = tid & 31;
    const int ray  = blockIdx.x;

    const int mi = wid >> 2;             // 0..3  -> rows 32*mi
    const int nj = wid & 3;              // 0..3  -> cols 64*nj

    float* sZ    = (float*)(sm + SM_Z);
    float* sWgt  = (float*)(sm + SM_WGT);
    float* sSig  = (float*)(sm + SM_SIG);
    float* sBW   = (float*)(sm + SM_BW);
    float* sRgb  = (float*)(sm + SM_RGB);
    float* sOutS = (float*)(sm + SM_OUTS);
    float* sBias = (float*)(sm + SM_BIAS);
    float* sW4f  = (float*)(sm + SM_W4);
    float* sHf   = (float*)(sm + BUF0);      // fp32 overlay (layer-3 out), stride HSTRIDE

    if (tid < SS) sZ[tid] = zv[(long)ray * SS + tid];

    // per-thread ldmatrix address components
    const int r8 = lane & 7, g = lane >> 3;
    const uint32_t aRow = (uint32_t)(32 * mi + (g & 1) * 8 + r8);
    const uint32_t aColOff = (uint32_t)((g >> 1) * 8);
    const uint32_t aHiBase = sbase + A_HI + (aRow * ASTRIDE + aColOff) * 2;
    const uint32_t bRow = (uint32_t)(nj * 64 + (g >> 1) * 8 + r8);
    const uint32_t bOff = (bRow * BSTRIDE + (g & 1) * 8) * 2;

    const int rowBase = 32 * mi + (lane >> 2);     // + 16*mb, +8 for c[2..3]
    const int colBase = nj * 64 + 2 * (lane & 3);  // + 8*nf

    for (int mlp = 0; mlp < 2; mlp++) {
        const float* const* Wp = mlp ? dy.W : st.W;
        const float* const* Bp = mlp ? dy.b : st.b;
        const int n4 = mlp ? 5 : 4;

        // ---- encode into fp32 scratch (overlays B buffers; all cp.async retired) ----
        CP_WAIT0();
        __syncthreads();
        float* scratch = (float*)(sm + BUF0);
        if (tid < SS) {
            const int m = tid;
            const long base = (long)ray * SS + m;
            const float p0 = pts[base*3+0], p1 = pts[base*3+1], p2 = pts[base*3+2];
            const float d0 = dir[base*3+0], d1 = dir[base*3+1], d2 = dir[base*3+2];
            const float t  = tim[base];
            float* x = scratch + m * 100;
            x[0] = p0; x[1] = p1; x[2] = p2;
            float f = 1.f; int o = 3;
#pragma unroll
            for (int l = 0; l < 10; l++) {
                float s0,c0,s1,c1,s2,c2;
                sincosf(f*p0,&s0,&c0); sincosf(f*p1,&s1,&c1); sincosf(f*p2,&s2,&c2);
                x[o]=s0; x[o+1]=s1; x[o+2]=s2; x[o+3]=c0; x[o+4]=c1; x[o+5]=c2;
                o += 6; f *= 2.f;
            }
            x[63]=d0; x[64]=d1; x[65]=d2;
            f = 1.f; o = 66;
#pragma unroll
            for (int l = 0; l < 4; l++) {
                float s0,c0,s1,c1,s2,c2;
                sincosf(f*d0,&s0,&c0); sincosf(f*d1,&s1,&c1); sincosf(f*d2,&s2,&c2);
                x[o]=s0; x[o+1]=s1; x[o+2]=s2; x[o+3]=c0; x[o+4]=c1; x[o+5]=c2;
                o += 6; f *= 2.f;
            }
            x[90]=t;
            f = 1.f; o = 91;
#pragma unroll
            for (int l = 0; l < 4; l++) {
                float s, c; sincosf(f*t, &s, &c);
                x[o]=s; x[o+1]=c; o += 2; f *= 2.f;
            }
        }
        __syncthreads();

        // ---- pack encodings to A plane (fp16), cols 0..127 (zero pad >=100) ----
        {
            const int m  = tid >> 2;
            const int j0 = (tid & 3) * 16;
            const float* xr = scratch + m * 100;
            uint32_t* aH = (uint32_t*)(sm + A_HI);
#pragma unroll
            for (int j = 0; j < 16; j++) {
                const int k0 = 2 * (j0 + j);
                const float v0 = (k0     < 100) ? xr[k0]     : 0.f;
                const float v1 = (k0 + 1 < 100) ? xr[k0 + 1] : 0.f;
                aH[m * (ASTRIDE/2) + j0 + j] = pack_h2(v0, v1);
            }
        }
        __syncthreads();

        // ---- prefetch chunks 0,1 ----
        int cg = 0;
        for (int pc = 0; pc < 2; pc++) {
            const char* srcH = (const char*)g_wimg[mlp][pc][0];
            const char* srcL = (const char*)g_wimg[mlp][pc][1];
            const uint32_t dstB = sbase + BUF0 + pc * BBUFSZ;
#pragma unroll
            for (int i = 0; i < 4; i++) {
                const int idx = tid + i * NTHREADS;         // 0..2047
                const uint32_t d = dstB + (uint32_t)(idx >> 3) * (BSTRIDE*2) + (idx & 7) * 16;
                cp16(d,          srcH + idx * 16);
                cp16(d + BPLANE, srcL + idx * 16);
            }
            CP_COMMIT();
        }

        for (int layer = 0; layer < 4; layer++) {
            // stage bias (+ final W4) for this layer (overlaps chunk wait)
            for (int i = tid; i < HID; i += NTHREADS) sBias[i] = __ldg(Bp[layer] + i);
            if (layer == 3)
                for (int i = tid; i < HID * n4; i += NTHREADS) sW4f[i] = __ldg(Wp[4] + i);

            float acc[16][4];
#pragma unroll
            for (int a = 0; a < 16; a++)
#pragma unroll
                for (int q = 0; q < 4; q++) acc[a][q] = 0.f;

            const int nch = (layer == 0) ? 2 : 4;
            for (int c = 0; c < nch; c++) {
                CP_WAIT1();                       // chunk cg resident
                __syncthreads();
                const uint32_t bB = sbase + BUF0 + (uint32_t)(cg & 1) * BBUFSZ + bOff;
                gemm_chunk(aHiBase + c * (KC * 2), bB, acc);
                __syncthreads();
                // prefetch chunk cg+2 into buf (cg&1); always commit (uniform group count)
                if (cg + 2 < NCHUNK) {
                    const int nc = cg + 2;
                    const char* srcH = (const char*)g_wimg[mlp][nc][0];
                    const char* srcL = (const char*)g_wimg[mlp][nc][1];
                    const uint32_t dstB = sbase + BUF0 + (uint32_t)(cg & 1) * BBUFSZ;
#pragma unroll
                    for (int i = 0; i < 4; i++) {
                        const int idx = tid + i * NTHREADS;
                        const uint32_t d = dstB + (uint32_t)(idx >> 3) * (BSTRIDE*2) + (idx & 7) * 16;
                        cp16(d,          srcH + idx * 16);
                        cp16(d + BPLANE, srcL + idx * 16);
                    }
                }
                CP_COMMIT();
                cg++;
            }

            // ---- epilogue ----
            if (layer < 3) {
                uint32_t* aH = (uint32_t*)(sm + A_HI);
#pragma unroll
                for (int idx = 0; idx < 16; idx++) {
                    const int mb = idx >> 3, nf = idx & 7;
                    const int row = rowBase + 16 * mb;
                    const int col = colBase + 8 * nf;
                    const float b0 = sBias[col], b1 = sBias[col + 1];
                    const float h00 = fmaxf(acc[idx][0] + b0, 0.f);
                    const float h01 = fmaxf(acc[idx][1] + b1, 0.f);
                    const float h10 = fmaxf(acc[idx][2] + b0, 0.f);
                    const float h11 = fmaxf(acc[idx][3] + b1, 0.f);
                    aH[row * (ASTRIDE/2) + (col >> 1)]       = pack_h2(h00, h01);
                    aH[(row + 8) * (ASTRIDE/2) + (col >> 1)] = pack_h2(h10, h11);
                }
            } else {
                // fp32 relu output into BUF0 overlay (B buffers idle: no pending prefetch)
#pragma unroll
                for (int idx = 0; idx < 16; idx++) {
                    const int mb = idx >> 3, nf = idx & 7;
                    const int row = rowBase + 16 * mb;
                    const int col = colBase + 8 * nf;
                    const float b0 = sBias[col], b1 = sBias[col + 1];
                    sHf[row * HSTRIDE + col]           = fmaxf(acc[idx][0] + b0, 0.f);
                    sHf[row * HSTRIDE + col + 1]       = fmaxf(acc[idx][1] + b1, 0.f);
                    sHf[(row + 8) * HSTRIDE + col]     = fmaxf(acc[idx][2] + b0, 0.f);
                    sHf[(row + 8) * HSTRIDE + col + 1] = fmaxf(acc[idx][3] + b1, 0.f);
                }
            }
            __syncthreads();
        }

        // ---- final 256 -> n4 dot: 2 threads per sample (k halves), shfl combine ----
        if (tid < 2 * SS) {
            const int m = tid >> 1, half = tid & 1;
            float o5[5];
            const float* b4 = Bp[4];
#pragma unroll
            for (int j = 0; j < 5; j++) o5[j] = (half == 0 && j < n4) ? __ldg(b4 + j) : 0.f;
            const float* arow = sHf + m * HSTRIDE + half * 128;
            for (int k = 0; k < 128; k += 4) {
                const float4 a = *reinterpret_cast<const float4*>(arow + k);
                const int kw = half * 128 + k;
#pragma unroll
                for (int kk = 0; kk < 4; kk++) {
                    const float av = (kk == 0) ? a.x : (kk == 1) ? a.y : (kk == 2) ? a.z : a.w;
#pragma unroll
                    for (int j = 0; j < 5; j++)
                        if (j < n4) o5[j] += av * sW4f[(kw + kk) * n4 + j];
                }
            }
#pragma unroll
            for (int j = 0; j < 5; j++) o5[j] += __shfl_xor_sync(0xffffffffu, o5[j], 1);
            if (half == 0) {
                if (mlp == 0) {
                    sOutS[m*4+0] = o5[0]; sOutS[m*4+1] = o5[1];
                    sOutS[m*4+2] = o5[2]; sOutS[m*4+3] = o5[3];
                } else {
                    const float bw = sigmoidf_(o5[4]);
                    sSig[m] = (1.f - bw) * sOutS[m*4+0] + bw * o5[0];
                    sBW[m]  = bw;
#pragma unroll
                    for (int cc = 0; cc < 3; cc++) {
                        const float rs = sigmoidf_(sOutS[m*4+1+cc]);
                        const float rd = sigmoidf_(o5[1+cc]);
                        sRgb[m*3+cc] = (1.f - bw) * rs + bw * rd;
                    }
                }
            }
        }
        __syncthreads();
    }

    // ---- parallel alpha, then warp-0 prefix-product scan + reductions ----
    float* sAlpha = sOutS;            // reuse (sOutS dead now)
    float* sOma   = sOutS + SS;
    if (tid < SS) {
        const float z = sZ[tid];
        const float delta = (tid < SS - 1) ? (sZ[tid + 1] - z) : 1e10f;
        const float alpha = 1.f - expf(-sSig[tid] * delta);
        sAlpha[tid] = alpha;
        sOma[tid]   = 1.f - alpha + 1e-10f;
    }
    __syncthreads();
    if (wid == 0) {
        float a[4], o[4], zr[4], rg[4][3];
#pragma unroll
        for (int j = 0; j < 4; j++) {
            const int m = 4 * lane + j;
            a[j] = sAlpha[m]; o[j] = sOma[m]; zr[j] = sZ[m];
            rg[j][0] = sRgb[m*3+0]; rg[j][1] = sRgb[m*3+1]; rg[j][2] = sRgb[m*3+2];
        }
        float run = o[0] * o[1] * o[2] * o[3];
#pragma unroll
        for (int d = 1; d < 32; d <<= 1) {
            const float v = __shfl_up_sync(0xffffffffu, run, d);
            if (lane >= d) run *= v;
        }
        float T = __shfl_up_sync(0xffffffffu, run, 1);
        if (lane == 0) T = 1.f;
        float r0 = 0.f, r1 = 0.f, r2 = 0.f, dep = 0.f;
#pragma unroll
        for (int j = 0; j < 4; j++) {
            const float w = a[j] * T;
            sWgt[4 * lane + j] = w;
            r0 += w * rg[j][0]; r1 += w * rg[j][1]; r2 += w * rg[j][2];
            dep += w * zr[j];
            T *= o[j];
        }
#pragma unroll
        for (int d = 16; d > 0; d >>= 1) {
            r0  += __shfl_xor_sync(0xffffffffu, r0, d);
            r1  += __shfl_xor_sync(0xffffffffu, r1, d);
            r2  += __shfl_xor_sync(0xffffffffu, r2, d);
            dep += __shfl_xor_sync(0xffffffffu, dep, d);
        }
        if (lane == 0) {
            out[ray*3+0] = r0; out[ray*3+1] = r1; out[ray*3+2] = r2;
            out[(long)R * 3 + ray] = dep;
        }
    }
    __syncthreads();

    if (tid < SS) {
        const int m = tid;
        const float w  = sWgt[m];
        const float bw = sBW[m];
        const long o = (long)ray * SS + m;
        const long base = (long)R * 4;
        const long rs = (long)R * SS;
        out[base + o]          = w;
        out[base + rs + o]     = (1.f - bw) * w;
        out[base + 2 * rs + o] = bw * w;
    }
}

extern "C" void kernel_launch(void* const* d_in, const int* in_sizes, int n_in,
                              void* d_out, int out_size)
{
    const float* pts = (const float*)d_in[0];
    const float* dir = (const float*)d_in[1];
    const float* zv  = (const float*)d_in[2];
    const float* tim = (const float*)d_in[3];

    MLPParams st, dy;
    for (int i = 0; i < 5; i++) {
        st.W[i] = (const float*)d_in[4 + 4 * i];
        st.b[i] = (const float*)d_in[5 + 4 * i];
        dy.W[i] = (const float*)d_in[6 + 4 * i];
        dy.b[i] = (const float*)d_in[7 + 4 * i];
    }

    const int R = in_sizes[2] / SS;

    prepass_kernel<<<2 * NCHUNK, 256>>>(st, dy);

    cudaFuncSetAttribute(nerf_main, cudaFuncAttributeMaxDynamicSharedMemorySize, SM_TOTAL);
    nerf_main<<<R, NTHREADS, SM_TOTAL>>>(pts, dir, zv, tim, st, dy, (float*)d_out, R);
}

// round 12
// speedup vs baseline: 1.5789x; 1.1090x over previous
#include <cuda_runtime.h>
#include <cuda_fp16.h>
#include <math.h>
#include <stdint.h>

// ---------------- problem constants ----------------
#define SS        128
#define HID       256
#define NTHREADS  512
#define KC        64               // K per weight chunk (fp16)
#define NCHUNK    14               // per MLP: layer0: 2 (Kpad=128), layers1-3: 4 each
#define ASTRIDE   264              // A plane row stride in fp16 (33*16B: conflict-free ldmatrix)
#define HSTRIDE   260              // fp32 overlay row stride
#define BSTRIDE   72               // B row stride fp16 (9*16B: odd -> conflict-free)
#define BPLANE_OFF 18432           // 128*72*2 bytes per plane (hi then lo)

// ---- shared memory byte offsets ----
#define A_HI      0                              // 128*264*2 = 67584
// per-group double buffers: group*73728 + buf*36864 (each buf = hi+lo planes)
#define BUFBASE   67584                          // 2 groups * 73728 = 147456 -> 215040
#define SM_W4     215040                         // 256*5*4 = 5120   -> 220160
#define SM_BIAS   220160                         // 256*4 = 1024     -> 221184
#define SM_OUTS   221184                         // 128*4*4 = 2048   -> 223232 (reused alpha/oma)
#define SM_SIG    223232
#define SM_BW     223744
#define SM_RGB    224256
#define SM_Z      225792
#define SM_WGT    226304
#define SM_TOTAL  226816
// layer-3 fp32 overlay (128*260*4 = 133120) overlays the B-buffer region (67584..200704)

// Pre-transposed fp16 hi/lo weight images per N-half: [mlp][chunk][nhalf][plane][128*64]
__device__ __align__(16) __half g_wimg[2][NCHUNK][2][2][128 * KC];

struct MLPParams { const float* W[5]; const float* b[5]; };

// ---------------- PTX helpers (all baseline sm_80 ISA) ----------------
__device__ __forceinline__ uint32_t smem_u32(const void* p) {
    uint32_t a;
    asm("{ .reg .u64 t; cvta.to.shared.u64 t, %1; cvt.u32.u64 %0, t; }" : "=r"(a) : "l"(p));
    return a;
}

#define LDSM4(r0, r1, r2, r3, addr) \
    asm volatile("ldmatrix.sync.aligned.m8n8.x4.shared.b16 {%0,%1,%2,%3}, [%4];" \
        : "=r"(r0), "=r"(r1), "=r"(r2), "=r"(r3) : "r"(addr))

#define MMA16816(c, a0, a1, a2, a3, b0, b1) \
    asm volatile("mma.sync.aligned.m16n8k16.row.col.f32.f16.f16.f32 " \
        "{%0,%1,%2,%3}, {%4,%5,%6,%7}, {%8,%9}, {%0,%1,%2,%3};" \
        : "+f"((c)[0]), "+f"((c)[1]), "+f"((c)[2]), "+f"((c)[3]) \
        : "r"(a0), "r"(a1), "r"(a2), "r"(a3), "r"(b0), "r"(b1))

__device__ __forceinline__ void cp16(uint32_t dst, const void* src) {
    asm volatile("cp.async.cg.shared.global [%0], [%1], 16;" :: "r"(dst), "l"(src));
}
#define CP_COMMIT() asm volatile("cp.async.commit_group;" ::: "memory")
#define CP_WAIT1()  asm volatile("cp.async.wait_group 1;" ::: "memory")
#define CP_WAIT0()  asm volatile("cp.async.wait_group 0;" ::: "memory")
#define GBAR(id)    asm volatile("bar.sync %0, 256;" :: "r"(id) : "memory")

__device__ __forceinline__ float sigmoidf_(float x) { return 1.0f / (1.0f + expf(-x)); }

__device__ __forceinline__ uint32_t pack_h2(float v0, float v1) {
    __half2 h = __floats2half2_rn(v0, v1);
    return *reinterpret_cast<uint32_t*>(&h);
}

// ---------------- pre-pass: [N-half=128][Kc=64] fp16 hi/lo images ----------------
__global__ void prepass_kernel(MLPParams st, MLPParams dy) {
    const int bi  = blockIdx.x;            // 0..55
    const int mlp = bi / (NCHUNK * 2);
    const int rem = bi % (NCHUNK * 2);
    const int c   = rem >> 1;
    const int nh  = rem & 1;
    const int layer = (c < 2) ? 0 : 1 + (c - 2) / 4;
    const int kbase = (c < 2) ? c * KC : ((c - 2) % 4) * KC;
    const float* W = mlp ? dy.W[layer] : st.W[layer];
    const int Kreal = (layer == 0) ? (mlp ? 99 : 90) : HID;

    __half* outH = g_wimg[mlp][c][nh][0];
    __half* outL = g_wimg[mlp][c][nh][1];
    const int n = threadIdx.x;             // 0..127 local N
    const int ng = nh * 128 + n;           // global N
    for (int k = 0; k < KC; k++) {
        const int kg = kbase + k;
        const float w = (kg < Kreal) ? __ldg(W + (size_t)kg * HID + ng) : 0.f;
        __half h = __float2half_rn(w);
        __half l = __float2half_rn(w - __half2float(h));
        outH[n * KC + k] = h;
        outL[n * KC + k] = l;
    }
}

// ---- software-pipelined GEMM chunk: warp tile 32(M) x 64(N), Kc=64, W hi/lo ----
__device__ __forceinline__ void gemm_chunk(uint32_t aBase, uint32_t bB, float acc[16][4]) {
    uint32_t a[2][8], b[2][8];
    LDSM4(a[0][0], a[0][1], a[0][2], a[0][3], aBase);
    LDSM4(a[0][4], a[0][5], a[0][6], a[0][7], aBase + 16 * (ASTRIDE * 2));
    LDSM4(b[0][0], b[0][1], b[0][2], b[0][3], bB);
    LDSM4(b[0][4], b[0][5], b[0][6], b[0][7], bB + BPLANE_OFF);
#pragma unroll
    for (int it = 0; it < 16; it++) {
        const int ks = it >> 2, nb = it & 3;
        const int cur = it & 1, nxt = cur ^ 1;
        if (it < 15) {
            const int nks = (it + 1) >> 2, nnb = (it + 1) & 3;
            const uint32_t nbk = bB + nks * 32 + nnb * (16 * BSTRIDE * 2);
            LDSM4(b[nxt][0], b[nxt][1], b[nxt][2], b[nxt][3], nbk);
            LDSM4(b[nxt][4], b[nxt][5], b[nxt][6], b[nxt][7], nbk + BPLANE_OFF);
        }
        if (nb == 0 && ks < 3) {
            const int ap = (ks + 1) & 1;
            const uint32_t na = aBase + (ks + 1) * 32;
            LDSM4(a[ap][0], a[ap][1], a[ap][2], a[ap][3], na);
            LDSM4(a[ap][4], a[ap][5], a[ap][6], a[ap][7], na + 16 * (ASTRIDE * 2));
        }
        const int p = ks & 1;
#pragma unroll
        for (int mb = 0; mb < 2; mb++) {
            float* c0 = acc[mb * 8 + 2 * nb];
            float* c1 = acc[mb * 8 + 2 * nb + 1];
            MMA16816(c0, a[p][mb*4+0], a[p][mb*4+1], a[p][mb*4+2], a[p][mb*4+3], b[cur][0], b[cur][1]);
            MMA16816(c1, a[p][mb*4+0], a[p][mb*4+1], a[p][mb*4+2], a[p][mb*4+3], b[cur][2], b[cur][3]);
            MMA16816(c0, a[p][mb*4+0], a[p][mb*4+1], a[p][mb*4+2], a[p][mb*4+3], b[cur][4], b[cur][5]);
            MMA16816(c1, a[p][mb*4+0], a[p][mb*4+1], a[p][mb*4+2], a[p][mb*4+3], b[cur][6], b[cur][7]);
        }
    }
}

// ---------------- main kernel ----------------
__global__ void __launch_bounds__(NTHREADS, 1)
nerf_main(const float* __restrict__ pts, const float* __restrict__ dir,
          const float* __restrict__ zv,  const float* __restrict__ tim,
          MLPParams st, MLPParams dy, float* __restrict__ out, int R)
{
    extern __shared__ char sm[];
    const uint32_t sbase = smem_u32(sm);

    const int tid  = threadIdx.x;
    const int wid  = tid >> 5;
    const int lane = tid & 31;
    const int ray  = blockIdx.x;

    const int group = wid >> 3;          // 0,1 -> N cols [0..127], [128..255]
    const int gw    = wid & 7;
    const int mi    = gw >> 1;           // 0..3 -> rows 32*mi
    const int njg   = gw & 1;            // 0..1 -> cols group*128 + njg*64
    const int gtid  = tid & 255;
    const uint32_t myBufBase = sbase + BUFBASE + (uint32_t)group * 73728u;

    float* sZ    = (float*)(sm + SM_Z);
    float* sWgt  = (float*)(sm + SM_WGT);
    float* sSig  = (float*)(sm + SM_SIG);
    float* sBW   = (float*)(sm + SM_BW);
    float* sRgb  = (float*)(sm + SM_RGB);
    float* sOutS = (float*)(sm + SM_OUTS);
    float* sBias = (float*)(sm + SM_BIAS);
    float* sW4f  = (float*)(sm + SM_W4);
    float* sHf   = (float*)(sm + BUFBASE);   // fp32 overlay (layer-3 out), stride HSTRIDE

    if (tid < SS) sZ[tid] = zv[(long)ray * SS + tid];

    // per-thread ldmatrix address components
    const int r8 = lane & 7, g = lane >> 3;
    const uint32_t aRow = (uint32_t)(32 * mi + (g & 1) * 8 + r8);
    const uint32_t aColOff = (uint32_t)((g >> 1) * 8);
    const uint32_t aHiBase = sbase + A_HI + (aRow * ASTRIDE + aColOff) * 2;
    const uint32_t bRow = (uint32_t)(njg * 64 + (g >> 1) * 8 + r8);   // local in group image
    const uint32_t bOff = (bRow * BSTRIDE + (g & 1) * 8) * 2;

    const int rowBase = 32 * mi + (lane >> 2);
    const int colBase = group * 128 + njg * 64 + 2 * (lane & 3);

    for (int mlp = 0; mlp < 2; mlp++) {
        const float* const* Wp = mlp ? dy.W : st.W;
        const float* const* Bp = mlp ? dy.b : st.b;
        const int n4 = mlp ? 5 : 4;

        CP_WAIT0();
        __syncthreads();       // B-buffer region (incl. sHf overlay) free for reuse

        // ---- encode directly into fp16 A plane, 4-way warp-uniform split ----
        {
            const int m = tid & 127;
            const int q = tid >> 7;
            const long base = (long)ray * SS + m;
            char* arow = sm + A_HI + (size_t)m * (ASTRIDE * 2);
#define STH(col, v) (*(__half*)(arow + (col) * 2) = __float2half_rn(v))
            if (q == 0) {
                const float p0 = pts[base*3+0], p1 = pts[base*3+1], p2 = pts[base*3+2];
                STH(0, p0); STH(1, p1); STH(2, p2);
                float f = 1.f;
#pragma unroll
                for (int l = 0; l < 5; l++) {
                    float s0,c0,s1,c1,s2,c2;
                    sincosf(f*p0,&s0,&c0); sincosf(f*p1,&s1,&c1); sincosf(f*p2,&s2,&c2);
                    const int o = 3 + 6*l;
                    STH(o,s0); STH(o+1,s1); STH(o+2,s2);
                    STH(o+3,c0); STH(o+4,c1); STH(o+5,c2);
                    f *= 2.f;
                }
            } else if (q == 1) {
                const float p0 = pts[base*3+0], p1 = pts[base*3+1], p2 = pts[base*3+2];
                float f = 32.f;
#pragma unroll
                for (int l = 0; l < 5; l++) {
                    float s0,c0,s1,c1,s2,c2;
                    sincosf(f*p0,&s0,&c0); sincosf(f*p1,&s1,&c1); sincosf(f*p2,&s2,&c2);
                    const int o = 33 + 6*l;
                    STH(o,s0); STH(o+1,s1); STH(o+2,s2);
                    STH(o+3,c0); STH(o+4,c1); STH(o+5,c2);
                    f *= 2.f;
                }
            } else if (q == 2) {
                const float d0 = dir[base*3+0], d1 = dir[base*3+1], d2 = dir[base*3+2];
                STH(63, d0); STH(64, d1); STH(65, d2);
                float f = 1.f;
#pragma unroll
                for (int l = 0; l < 4; l++) {
                    float s0,c0,s1,c1,s2,c2;
                    sincosf(f*d0,&s0,&c0); sincosf(f*d1,&s1,&c1); sincosf(f*d2,&s2,&c2);
                    const int o = 66 + 6*l;
                    STH(o,s0); STH(o+1,s1); STH(o+2,s2);
                    STH(o+3,c0); STH(o+4,c1); STH(o+5,c2);
                    f *= 2.f;
                }
            } else {
                const float t = tim[base];
                STH(90, t);
                float f = 1.f;
#pragma unroll
                for (int l = 0; l < 4; l++) {
                    float s, c; sincosf(f*t, &s, &c);
                    STH(91 + 2*l, s); STH(92 + 2*l, c);
                    f *= 2.f;
                }
#pragma unroll
                for (int col = 99; col < 128; col++) STH(col, 0.f);
            }
#undef STH
        }
        __syncthreads();

        // ---- per-group prefetch of chunks 0,1 (flat 2048x16B copy per chunk) ----
        int cg = 0;
        for (int pc = 0; pc < 2; pc++) {
            const char* src = (const char*)g_wimg[mlp][pc][group];
            const uint32_t dstB = myBufBase + (uint32_t)pc * 36864u;
#pragma unroll
            for (int i = 0; i < 8; i++) {
                const int idx = gtid + i * 256;                  // 0..2047
                const int plane = idx >> 10;
                const int ru = idx & 1023;
                const uint32_t d = dstB + (uint32_t)plane * BPLANE_OFF
                                 + (uint32_t)(ru >> 3) * (BSTRIDE * 2) + (ru & 7) * 16;
                cp16(d, src + idx * 16);
            }
            CP_COMMIT();
        }

        for (int layer = 0; layer < 4; layer++) {
            for (int i = tid; i < HID; i += NTHREADS) sBias[i] = __ldg(Bp[layer] + i);
            if (layer == 3)
                for (int i = tid; i < HID * n4; i += NTHREADS) sW4f[i] = __ldg(Wp[4] + i);

            float acc[16][4];
#pragma unroll
            for (int a = 0; a < 16; a++)
#pragma unroll
                for (int q = 0; q < 4; q++) acc[a][q] = 0.f;

            const int nch = (layer == 0) ? 2 : 4;
            for (int c = 0; c < nch; c++) {
                CP_WAIT1();                        // group's chunk cg resident
                GBAR(1 + group);
                const uint32_t bB = myBufBase + (uint32_t)(cg & 1) * 36864u + bOff;
                gemm_chunk(aHiBase + c * (KC * 2), bB, acc);
                GBAR(1 + group);                   // group done reading buf (cg&1)
                if (cg + 2 < NCHUNK) {
                    const char* src = (const char*)g_wimg[mlp][cg + 2][group];
                    const uint32_t dstB = myBufBase + (uint32_t)(cg & 1) * 36864u;
#pragma unroll
                    for (int i = 0; i < 8; i++) {
                        const int idx = gtid + i * 256;
                        const int plane = idx >> 10;
                        const int ru = idx & 1023;
                        const uint32_t d = dstB + (uint32_t)plane * BPLANE_OFF
                                         + (uint32_t)(ru >> 3) * (BSTRIDE * 2) + (ru & 7) * 16;
                        cp16(d, src + idx * 16);
                    }
                }
                CP_COMMIT();                       // uniform group count
                cg++;
            }

            __syncthreads();   // both groups finished reading A before in-place write

            if (layer < 3) {
                uint32_t* aH = (uint32_t*)(sm + A_HI);
#pragma unroll
                for (int idx = 0; idx < 16; idx++) {
                    const int mb = idx >> 3, nf = idx & 7;
                    const int row = rowBase + 16 * mb;
                    const int col = colBase + 8 * nf;
                    const float b0 = sBias[col], b1 = sBias[col + 1];
                    const float h00 = fmaxf(acc[idx][0] + b0, 0.f);
                    const float h01 = fmaxf(acc[idx][1] + b1, 0.f);
                    const float h10 = fmaxf(acc[idx][2] + b0, 0.f);
                    const float h11 = fmaxf(acc[idx][3] + b1, 0.f);
                    aH[row * (ASTRIDE/2) + (col >> 1)]       = pack_h2(h00, h01);
                    aH[(row + 8) * (ASTRIDE/2) + (col >> 1)] = pack_h2(h10, h11);
                }
            } else {
                // fp32 relu output into B-buffer overlay (all prefetches consumed)
#pragma unroll
                for (int idx = 0; idx < 16; idx++) {
                    const int mb = idx >> 3, nf = idx & 7;
                    const int row = rowBase + 16 * mb;
                    const int col = colBase + 8 * nf;
                    const float b0 = sBias[col], b1 = sBias[col + 1];
                    sHf[row * HSTRIDE + col]           = fmaxf(acc[idx][0] + b0, 0.f);
                    sHf[row * HSTRIDE + col + 1]       = fmaxf(acc[idx][1] + b1, 0.f);
                    sHf[(row + 8) * HSTRIDE + col]     = fmaxf(acc[idx][2] + b0, 0.f);
                    sHf[(row + 8) * HSTRIDE + col + 1] = fmaxf(acc[idx][3] + b1, 0.f);
                }
            }
            __syncthreads();
        }

        // ---- final 256 -> n4 dot: 2 threads per sample, shfl combine ----
        if (tid < 2 * SS) {
            const int m = tid >> 1, half = tid & 1;
            float o5[5];
            const float* b4 = Bp[4];
#pragma unroll
            for (int j = 0; j < 5; j++) o5[j] = (half == 0 && j < n4) ? __ldg(b4 + j) : 0.f;
            const float* arow = sHf + m * HSTRIDE + half * 128;
            for (int k = 0; k < 128; k += 4) {
                const float4 a = *reinterpret_cast<const float4*>(arow + k);
                const int kw = half * 128 + k;
#pragma unroll
                for (int kk = 0; kk < 4; kk++) {
                    const float av = (kk == 0) ? a.x : (kk == 1) ? a.y : (kk == 2) ? a.z : a.w;
#pragma unroll
                    for (int j = 0; j < 5; j++)
                        if (j < n4) o5[j] += av * sW4f[(kw + kk) * n4 + j];
                }
            }
#pragma unroll
            for (int j = 0; j < 5; j++) o5[j] += __shfl_xor_sync(0xffffffffu, o5[j], 1);
            if (half == 0) {
                if (mlp == 0) {
                    sOutS[m*4+0] = o5[0]; sOutS[m*4+1] = o5[1];
                    sOutS[m*4+2] = o5[2]; sOutS[m*4+3] = o5[3];
                } else {
                    const float bw = sigmoidf_(o5[4]);
                    sSig[m] = (1.f - bw) * sOutS[m*4+0] + bw * o5[0];
                    sBW[m]  = bw;
#pragma unroll
                    for (int cc = 0; cc < 3; cc++) {
                        const float rs = sigmoidf_(sOutS[m*4+1+cc]);
                        const float rd = sigmoidf_(o5[1+cc]);
                        sRgb[m*3+cc] = (1.f - bw) * rs + bw * rd;
                    }
                }
            }
        }
        __syncthreads();
    }

    // ---- parallel alpha, then warp-0 prefix-product scan + reductions ----
    float* sAlpha = sOutS;            // reuse (sOutS dead now)
    float* sOma   = sOutS + SS;
    if (tid < SS) {
        const float z = sZ[tid];
        const float delta = (tid < SS - 1) ? (sZ[tid + 1] - z) : 1e10f;
        const float alpha = 1.f - expf(-sSig[tid] * delta);
        sAlpha[tid] = alpha;
        sOma[tid]   = 1.f - alpha + 1e-10f;
    }
    __syncthreads();
    if (wid == 0) {
        float a[4], o[4], zr[4], rg[4][3];
#pragma unroll
        for (int j = 0; j < 4; j++) {
            const int m = 4 * lane + j;
            a[j] = sAlpha[m]; o[j] = sOma[m]; zr[j] = sZ[m];
            rg[j][0] = sRgb[m*3+0]; rg[j][1] = sRgb[m*3+1]; rg[j][2] = sRgb[m*3+2];
        }
        float run = o[0] * o[1] * o[2] * o[3];
#pragma unroll
        for (int d = 1; d < 32; d <<= 1) {
            const float v = __shfl_up_sync(0xffffffffu, run, d);
            if (lane >= d) run *= v;
        }
        float T = __shfl_up_sync(0xffffffffu, run, 1);
        if (lane == 0) T = 1.f;
        float r0 = 0.f, r1 = 0.f, r2 = 0.f, dep = 0.f;
#pragma unroll
        for (int j = 0; j < 4; j++) {
            const float w = a[j] * T;
            sWgt[4 * lane + j] = w;
            r0 += w * rg[j][0]; r1 += w * rg[j][1]; r2 += w * rg[j][2];
            dep += w * zr[j];
            T *= o[j];
        }
#pragma unroll
        for (int d = 16; d > 0; d >>= 1) {
            r0  += __shfl_xor_sync(0xffffffffu, r0, d);
            r1  += __shfl_xor_sync(0xffffffffu, r1, d);
            r2  += __shfl_xor_sync(0xffffffffu, r2, d);
            dep += __shfl_xor_sync(0xffffffffu, dep, d);
        }
        if (lane == 0) {
            out[ray*3+0] = r0; out[ray*3+1] = r1; out[ray*3+2] = r2;
            out[(long)R * 3 + ray] = dep;
        }
    }
    __syncthreads();

    if (tid < SS) {
        const int m = tid;
        const float w  = sWgt[m];
        const float bw = sBW[m];
        const long o = (long)ray * SS + m;
        const long base = (long)R * 4;
        const long rs = (long)R * SS;
        out[base + o]          = w;
        out[base + rs + o]     = (1.f - bw) * w;
        out[base + 2 * rs + o] = bw * w;
    }
}

extern "C" void kernel_launch(void* const* d_in, const int* in_sizes, int n_in,
                              void* d_out, int out_size)
{
    const float* pts = (const float*)d_in[0];
    const float* dir = (const float*)d_in[1];
    const float* zv  = (const float*)d_in[2];
    const float* tim = (const float*)d_in[3];

    MLPParams st, dy;
    for (int i = 0; i < 5; i++) {
        st.W[i] = (const float*)d_in[4 + 4 * i];
        st.b[i] = (const float*)d_in[5 + 4 * i];
        dy.W[i] = (const float*)d_in[6 + 4 * i];
        dy.b[i] = (const float*)d_in[7 + 4 * i];
    }

    const int R = in_sizes[2] / SS;

    prepass_kernel<<<2 * NCHUNK * 2, 128>>>(st, dy);

    cudaFuncSetAttribute(nerf_main, cudaFuncAttributeMaxDynamicSharedMemorySize, SM_TOTAL);
    nerf_main<<<R, NTHREADS, SM_TOTAL>>>(pts, dir, zv, tim, st, dy, (float*)d_out, R);
}

// round 13
// speedup vs baseline: 1.6082x; 1.0186x over previous
#include <cuda_runtime.h>
#include <cuda_fp16.h>
#include <math.h>
#include <stdint.h>

// ---------------- problem constants ----------------
#define SS        128
#define HID       256
#define NTHREADS  512
#define KC        64               // K per weight chunk (fp16)
#define NCHUNK    14               // per MLP: layer0: 2 (Kpad=128), layers1-3: 4 each
#define ASTRIDE   264              // A plane row stride in fp16 (33*16B: conflict-free ldmatrix)
#define HSTRIDE   260              // fp32 overlay row stride
#define BSTRIDE   72               // B row stride fp16 (9*16B: odd -> conflict-free)
#define BPLANE_OFF 18432           // 128*72*2 bytes per plane (hi then lo)

// ---- shared memory byte offsets ----
#define A_HI      0                              // 128*264*2 = 67584
// per-group double buffers: group*73728 + buf*36864 (each buf = hi+lo planes)
#define BUFBASE   67584                          // 2 groups * 73728 = 147456 -> 215040
#define SM_W4     215040                         // 256*5*4 = 5120   -> 220160
#define SM_BIAS   220160                         // 256*4 = 1024     -> 221184
#define SM_OUTS   221184                         // 128*4*4 = 2048   -> 223232 (reused alpha/oma)
#define SM_SIG    223232
#define SM_BW     223744
#define SM_RGB    224256
#define SM_Z      225792
#define SM_WGT    226304
#define SM_TOTAL  226816
// layer-3 fp32 overlay (128*260*4 = 133120) overlays the B-buffer region (67584..200704)

// Pre-transposed fp16 hi/lo weight images per N-half: [mlp][chunk][nhalf][plane][128*64]
__device__ __align__(16) __half g_wimg[2][NCHUNK][2][2][128 * KC];

struct MLPParams { const float* W[5]; const float* b[5]; };

// ---------------- PTX helpers (all baseline sm_80 ISA) ----------------
__device__ __forceinline__ uint32_t smem_u32(const void* p) {
    uint32_t a;
    asm("{ .reg .u64 t; cvta.to.shared.u64 t, %1; cvt.u32.u64 %0, t; }" : "=r"(a) : "l"(p));
    return a;
}

#define LDSM4(r0, r1, r2, r3, addr) \
    asm volatile("ldmatrix.sync.aligned.m8n8.x4.shared.b16 {%0,%1,%2,%3}, [%4];" \
        : "=r"(r0), "=r"(r1), "=r"(r2), "=r"(r3) : "r"(addr))

#define MMA16816(c, a0, a1, a2, a3, b0, b1) \
    asm volatile("mma.sync.aligned.m16n8k16.row.col.f32.f16.f16.f32 " \
        "{%0,%1,%2,%3}, {%4,%5,%6,%7}, {%8,%9}, {%0,%1,%2,%3};" \
        : "+f"((c)[0]), "+f"((c)[1]), "+f"((c)[2]), "+f"((c)[3]) \
        : "r"(a0), "r"(a1), "r"(a2), "r"(a3), "r"(b0), "r"(b1))

__device__ __forceinline__ void cp16(uint32_t dst, const void* src) {
    asm volatile("cp.async.cg.shared.global [%0], [%1], 16;" :: "r"(dst), "l"(src));
}
#define CP_COMMIT() asm volatile("cp.async.commit_group;" ::: "memory")
#define CP_WAIT1()  asm volatile("cp.async.wait_group 1;" ::: "memory")
#define CP_WAIT0()  asm volatile("cp.async.wait_group 0;" ::: "memory")
#define GBAR(id)    asm volatile("bar.sync %0, 256;" :: "r"(id) : "memory")

__device__ __forceinline__ float sigmoidf_(float x) { return 1.0f / (1.0f + expf(-x)); }

__device__ __forceinline__ uint32_t pack_h2(float v0, float v1) {
    __half2 h = __floats2half2_rn(v0, v1);
    return *reinterpret_cast<uint32_t*>(&h);
}

// ---------------- pre-pass: [N-half=128][Kc=64] fp16 hi/lo images ----------------
__global__ void prepass_kernel(MLPParams st, MLPParams dy) {
    const int bi  = blockIdx.x;            // 0..55
    const int mlp = bi / (NCHUNK * 2);
    const int rem = bi % (NCHUNK * 2);
    const int c   = rem >> 1;
    const int nh  = rem & 1;
    const int layer = (c < 2) ? 0 : 1 + (c - 2) / 4;
    const int kbase = (c < 2) ? c * KC : ((c - 2) % 4) * KC;
    const float* W = mlp ? dy.W[layer] : st.W[layer];
    const int Kreal = (layer == 0) ? (mlp ? 99 : 90) : HID;

    __half* outH = g_wimg[mlp][c][nh][0];
    __half* outL = g_wimg[mlp][c][nh][1];
    const int n = threadIdx.x;             // 0..127 local N
    const int ng = nh * 128 + n;           // global N
    for (int k = 0; k < KC; k++) {
        const int kg = kbase + k;
        const float w = (kg < Kreal) ? __ldg(W + (size_t)kg * HID + ng) : 0.f;
        __half h = __float2half_rn(w);
        __half l = __float2half_rn(w - __half2float(h));
        outH[n * KC + k] = h;
        outL[n * KC + k] = l;
    }
}

// ---- GEMM chunk: warp tile 64(M) x 32(N), Kc=64, W hi/lo, B double-buffered ----
// acc index: ms*4 + nf  (ms 0..3 = 16-row block, nf 0..3 = n8 fragment)
__device__ __forceinline__ void gemm_chunk(uint32_t aBase, uint32_t bB, float acc[16][4]) {
    uint32_t b[2][16];
    // B regs per ks: [ns*4 + 0..3] = hi plane n16 group ns; [8 + ns*4 + 0..3] = lo plane
#pragma unroll
    for (int ns = 0; ns < 2; ns++) {
        LDSM4(b[0][ns*4+0], b[0][ns*4+1], b[0][ns*4+2], b[0][ns*4+3],
              bB + ns * (16 * BSTRIDE * 2));
        LDSM4(b[0][8+ns*4+0], b[0][8+ns*4+1], b[0][8+ns*4+2], b[0][8+ns*4+3],
              bB + BPLANE_OFF + ns * (16 * BSTRIDE * 2));
    }
#pragma unroll
    for (int ks = 0; ks < 4; ks++) {
        const int cur = ks & 1, nxt = cur ^ 1;
        if (ks < 3) {
            const uint32_t nbk = bB + (ks + 1) * 32;
#pragma unroll
            for (int ns = 0; ns < 2; ns++) {
                LDSM4(b[nxt][ns*4+0], b[nxt][ns*4+1], b[nxt][ns*4+2], b[nxt][ns*4+3],
                      nbk + ns * (16 * BSTRIDE * 2));
                LDSM4(b[nxt][8+ns*4+0], b[nxt][8+ns*4+1], b[nxt][8+ns*4+2], b[nxt][8+ns*4+3],
                      nbk + BPLANE_OFF + ns * (16 * BSTRIDE * 2));
            }
        }
        uint32_t a[16];
#pragma unroll
        for (int ms = 0; ms < 4; ms++)
            LDSM4(a[ms*4+0], a[ms*4+1], a[ms*4+2], a[ms*4+3],
                  aBase + ks * 32 + ms * (16 * ASTRIDE * 2));
#pragma unroll
        for (int ms = 0; ms < 4; ms++) {
#pragma unroll
            for (int ns = 0; ns < 2; ns++) {
                float* c0 = acc[ms * 4 + ns * 2];
                float* c1 = acc[ms * 4 + ns * 2 + 1];
                MMA16816(c0, a[ms*4+0], a[ms*4+1], a[ms*4+2], a[ms*4+3],
                         b[cur][ns*4+0], b[cur][ns*4+1]);
                MMA16816(c1, a[ms*4+0], a[ms*4+1], a[ms*4+2], a[ms*4+3],
                         b[cur][ns*4+2], b[cur][ns*4+3]);
                MMA16816(c0, a[ms*4+0], a[ms*4+1], a[ms*4+2], a[ms*4+3],
                         b[cur][8+ns*4+0], b[cur][8+ns*4+1]);
                MMA16816(c1, a[ms*4+0], a[ms*4+1], a[ms*4+2], a[ms*4+3],
                         b[cur][8+ns*4+2], b[cur][8+ns*4+3]);
            }
        }
    }
}

// ---------------- main kernel ----------------
__global__ void __launch_bounds__(NTHREADS, 1)
nerf_main(const float* __restrict__ pts, const float* __restrict__ dir,
          const float* __restrict__ zv,  const float* __restrict__ tim,
          MLPParams st, MLPParams dy, float* __restrict__ out, int R)
{
    extern __shared__ char sm[];
    const uint32_t sbase = smem_u32(sm);

    const int tid  = threadIdx.x;
    const int wid  = tid >> 5;
    const int lane = tid & 31;
    const int ray  = blockIdx.x;

    const int group = wid >> 3;          // 0,1 -> N cols [0..127], [128..255]
    const int gw    = wid & 7;
    const int mi    = gw >> 2;           // 0..1 -> rows 64*mi
    const int njg   = gw & 3;            // 0..3 -> cols group*128 + njg*32
    const int gtid  = tid & 255;
    const uint32_t myBufBase = sbase + BUFBASE + (uint32_t)group * 73728u;

    float* sZ    = (float*)(sm + SM_Z);
    float* sWgt  = (float*)(sm + SM_WGT);
    float* sSig  = (float*)(sm + SM_SIG);
    float* sBW   = (float*)(sm + SM_BW);
    float* sRgb  = (float*)(sm + SM_RGB);
    float* sOutS = (float*)(sm + SM_OUTS);
    float* sBias = (float*)(sm + SM_BIAS);
    float* sW4f  = (float*)(sm + SM_W4);
    float* sHf   = (float*)(sm + BUFBASE);   // fp32 overlay (layer-3 out), stride HSTRIDE

    if (tid < SS) sZ[tid] = zv[(long)ray * SS + tid];

    // per-thread ldmatrix address components
    const int r8 = lane & 7, g = lane >> 3;
    const uint32_t aRow = (uint32_t)(64 * mi + (g & 1) * 8 + r8);
    const uint32_t aColOff = (uint32_t)((g >> 1) * 8);
    const uint32_t aHiBase = sbase + A_HI + (aRow * ASTRIDE + aColOff) * 2;
    const uint32_t bRow = (uint32_t)(njg * 32 + (g >> 1) * 8 + r8);   // local in group image
    const uint32_t bOff = (bRow * BSTRIDE + (g & 1) * 8) * 2;

    const int rowBase = 64 * mi + (lane >> 2);       // + 16*ms, +8 for c[2..3]
    const int colBase = group * 128 + njg * 32 + 2 * (lane & 3);   // + 8*nf

    for (int mlp = 0; mlp < 2; mlp++) {
        const float* const* Wp = mlp ? dy.W : st.W;
        const float* const* Bp = mlp ? dy.b : st.b;
        const int n4 = mlp ? 5 : 4;

        CP_WAIT0();
        __syncthreads();       // B-buffer region (incl. sHf overlay) free for reuse

        // ---- encode directly into fp16 A plane, 4-way warp-uniform split ----
        {
            const int m = tid & 127;
            const int q = tid >> 7;
            const long base = (long)ray * SS + m;
            char* arow = sm + A_HI + (size_t)m * (ASTRIDE * 2);
#define STH(col, v) (*(__half*)(arow + (col) * 2) = __float2half_rn(v))
            if (q == 0) {
                const float p0 = pts[base*3+0], p1 = pts[base*3+1], p2 = pts[base*3+2];
                STH(0, p0); STH(1, p1); STH(2, p2);
                float f = 1.f;
#pragma unroll
                for (int l = 0; l < 5; l++) {
                    float s0,c0,s1,c1,s2,c2;
                    sincosf(f*p0,&s0,&c0); sincosf(f*p1,&s1,&c1); sincosf(f*p2,&s2,&c2);
                    const int o = 3 + 6*l;
                    STH(o,s0); STH(o+1,s1); STH(o+2,s2);
                    STH(o+3,c0); STH(o+4,c1); STH(o+5,c2);
                    f *= 2.f;
                }
            } else if (q == 1) {
                const float p0 = pts[base*3+0], p1 = pts[base*3+1], p2 = pts[base*3+2];
                float f = 32.f;
#pragma unroll
                for (int l = 0; l < 5; l++) {
                    float s0,c0,s1,c1,s2,c2;
                    sincosf(f*p0,&s0,&c0); sincosf(f*p1,&s1,&c1); sincosf(f*p2,&s2,&c2);
                    const int o = 33 + 6*l;
                    STH(o,s0); STH(o+1,s1); STH(o+2,s2);
                    STH(o+3,c0); STH(o+4,c1); STH(o+5,c2);
                    f *= 2.f;
                }
            } else if (q == 2) {
                const float d0 = dir[base*3+0], d1 = dir[base*3+1], d2 = dir[base*3+2];
                STH(63, d0); STH(64, d1); STH(65, d2);
                float f = 1.f;
#pragma unroll
                for (int l = 0; l < 4; l++) {
                    float s0,c0,s1,c1,s2,c2;
                    sincosf(f*d0,&s0,&c0); sincosf(f*d1,&s1,&c1); sincosf(f*d2,&s2,&c2);
                    const int o = 66 + 6*l;
                    STH(o,s0); STH(o+1,s1); STH(o+2,s2);
                    STH(o+3,c0); STH(o+4,c1); STH(o+5,c2);
                    f *= 2.f;
                }
            } else {
                const float t = tim[base];
                STH(90, t);
                float f = 1.f;
#pragma unroll
                for (int l = 0; l < 4; l++) {
                    float s, c; sincosf(f*t, &s, &c);
                    STH(91 + 2*l, s); STH(92 + 2*l, c);
                    f *= 2.f;
                }
#pragma unroll
                for (int col = 99; col < 128; col++) STH(col, 0.f);
            }
#undef STH
        }
        __syncthreads();

        // ---- per-group prefetch of chunks 0,1 (flat 2048x16B copy per chunk) ----
        int cg = 0;
        for (int pc = 0; pc < 2; pc++) {
            const char* src = (const char*)g_wimg[mlp][pc][group];
            const uint32_t dstB = myBufBase + (uint32_t)pc * 36864u;
#pragma unroll
            for (int i = 0; i < 8; i++) {
                const int idx = gtid + i * 256;                  // 0..2047
                const int plane = idx >> 10;
                const int ru = idx & 1023;
                const uint32_t d = dstB + (uint32_t)plane * BPLANE_OFF
                                 + (uint32_t)(ru >> 3) * (BSTRIDE * 2) + (ru & 7) * 16;
                cp16(d, src + idx * 16);
            }
            CP_COMMIT();
        }

        for (int layer = 0; layer < 4; layer++) {
            for (int i = tid; i < HID; i += NTHREADS) sBias[i] = __ldg(Bp[layer] + i);
            if (layer == 3)
                for (int i = tid; i < HID * n4; i += NTHREADS) sW4f[i] = __ldg(Wp[4] + i);

            float acc[16][4];
#pragma unroll
            for (int a = 0; a < 16; a++)
#pragma unroll
                for (int q = 0; q < 4; q++) acc[a][q] = 0.f;

            const int nch = (layer == 0) ? 2 : 4;
            for (int c = 0; c < nch; c++) {
                CP_WAIT1();                        // group's chunk cg resident
                GBAR(1 + group);
                const uint32_t bB = myBufBase + (uint32_t)(cg & 1) * 36864u + bOff;
                gemm_chunk(aHiBase + c * (KC * 2), bB, acc);
                GBAR(1 + group);                   // group done reading buf (cg&1)
                if (cg + 2 < NCHUNK) {
                    const char* src = (const char*)g_wimg[mlp][cg + 2][group];
                    const uint32_t dstB = myBufBase + (uint32_t)(cg & 1) * 36864u;
#pragma unroll
                    for (int i = 0; i < 8; i++) {
                        const int idx = gtid + i * 256;
                        const int plane = idx >> 10;
                        const int ru = idx & 1023;
                        const uint32_t d = dstB + (uint32_t)plane * BPLANE_OFF
                                         + (uint32_t)(ru >> 3) * (BSTRIDE * 2) + (ru & 7) * 16;
                        cp16(d, src + idx * 16);
                    }
                }
                CP_COMMIT();                       // uniform group count
                cg++;
            }

            __syncthreads();   // both groups finished reading A before in-place write

            if (layer < 3) {
                uint32_t* aH = (uint32_t*)(sm + A_HI);
#pragma unroll
                for (int idx = 0; idx < 16; idx++) {
                    const int ms = idx >> 2, nf = idx & 3;
                    const int row = rowBase + 16 * ms;
                    const int col = colBase + 8 * nf;
                    const float b0 = sBias[col], b1 = sBias[col + 1];
                    const float h00 = fmaxf(acc[idx][0] + b0, 0.f);
                    const float h01 = fmaxf(acc[idx][1] + b1, 0.f);
                    const float h10 = fmaxf(acc[idx][2] + b0, 0.f);
                    const float h11 = fmaxf(acc[idx][3] + b1, 0.f);
                    aH[row * (ASTRIDE/2) + (col >> 1)]       = pack_h2(h00, h01);
                    aH[(row + 8) * (ASTRIDE/2) + (col >> 1)] = pack_h2(h10, h11);
                }
            } else {
                // fp32 relu output into B-buffer overlay (all prefetches consumed)
#pragma unroll
                for (int idx = 0; idx < 16; idx++) {
                    const int ms = idx >> 2, nf = idx & 3;
                    const int row = rowBase + 16 * ms;
                    const int col = colBase + 8 * nf;
                    const float b0 = sBias[col], b1 = sBias[col + 1];
                    sHf[row * HSTRIDE + col]           = fmaxf(acc[idx][0] + b0, 0.f);
                    sHf[row * HSTRIDE + col + 1]       = fmaxf(acc[idx][1] + b1, 0.f);
                    sHf[(row + 8) * HSTRIDE + col]     = fmaxf(acc[idx][2] + b0, 0.f);
                    sHf[(row + 8) * HSTRIDE + col + 1] = fmaxf(acc[idx][3] + b1, 0.f);
                }
            }
            __syncthreads();
        }

        // ---- final 256 -> n4 dot: 2 threads per sample, shfl combine ----
        if (tid < 2 * SS) {
            const int m = tid >> 1, half = tid & 1;
            float o5[5];
            const float* b4 = Bp[4];
#pragma unroll
            for (int j = 0; j < 5; j++) o5[j] = (half == 0 && j < n4) ? __ldg(b4 + j) : 0.f;
            const float* arow = sHf + m * HSTRIDE + half * 128;
            for (int k = 0; k < 128; k += 4) {
                const float4 a = *reinterpret_cast<const float4*>(arow + k);
                const int kw = half * 128 + k;
#pragma unroll
                for (int kk = 0; kk < 4; kk++) {
                    const float av = (kk == 0) ? a.x : (kk == 1) ? a.y : (kk == 2) ? a.z : a.w;
#pragma unroll
                    for (int j = 0; j < 5; j++)
                        if (j < n4) o5[j] += av * sW4f[(kw + kk) * n4 + j];
                }
            }
#pragma unroll
            for (int j = 0; j < 5; j++) o5[j] += __shfl_xor_sync(0xffffffffu, o5[j], 1);
            if (half == 0) {
                if (mlp == 0) {
                    sOutS[m*4+0] = o5[0]; sOutS[m*4+1] = o5[1];
                    sOutS[m*4+2] = o5[2]; sOutS[m*4+3] = o5[3];
                } else {
                    const float bw = sigmoidf_(o5[4]);
                    sSig[m] = (1.f - bw) * sOutS[m*4+0] + bw * o5[0];
                    sBW[m]  = bw;
#pragma unroll
                    for (int cc = 0; cc < 3; cc++) {
                        const float rs = sigmoidf_(sOutS[m*4+1+cc]);
                        const float rd = sigmoidf_(o5[1+cc]);
                        sRgb[m*3+cc] = (1.f - bw) * rs + bw * rd;
                    }
                }
            }
        }
        __syncthreads();
    }

    // ---- parallel alpha, then warp-0 prefix-product scan + reductions ----
    float* sAlpha = sOutS;            // reuse (sOutS dead now)
    float* sOma   = sOutS + SS;
    if (tid < SS) {
        const float z = sZ[tid];
        const float delta = (tid < SS - 1) ? (sZ[tid + 1] - z) : 1e10f;
        const float alpha = 1.f - expf(-sSig[tid] * delta);
        sAlpha[tid] = alpha;
        sOma[tid]   = 1.f - alpha + 1e-10f;
    }
    __syncthreads();
    if (wid == 0) {
        float a[4], o[4], zr[4], rg[4][3];
#pragma unroll
        for (int j = 0; j < 4; j++) {
            const int m = 4 * lane + j;
            a[j] = sAlpha[m]; o[j] = sOma[m]; zr[j] = sZ[m];
            rg[j][0] = sRgb[m*3+0]; rg[j][1] = sRgb[m*3+1]; rg[j][2] = sRgb[m*3+2];
        }
        float run = o[0] * o[1] * o[2] * o[3];
#pragma unroll
        for (int d = 1; d < 32; d <<= 1) {
            const float v = __shfl_up_sync(0xffffffffu, run, d);
            if (lane >= d) run *= v;
        }
        float T = __shfl_up_sync(0xffffffffu, run, 1);
        if (lane == 0) T = 1.f;
        float r0 = 0.f, r1 = 0.f, r2 = 0.f, dep = 0.f;
#pragma unroll
        for (int j = 0; j < 4; j++) {
            const float w = a[j] * T;
            sWgt[4 * lane + j] = w;
            r0 += w * rg[j][0]; r1 += w * rg[j][1]; r2 += w * rg[j][2];
            dep += w * zr[j];
            T *= o[j];
        }
#pragma unroll
        for (int d = 16; d > 0; d >>= 1) {
            r0  += __shfl_xor_sync(0xffffffffu, r0, d);
            r1  += __shfl_xor_sync(0xffffffffu, r1, d);
            r2  += __shfl_xor_sync(0xffffffffu, r2, d);
            dep += __shfl_xor_sync(0xffffffffu, dep, d);
        }
        if (lane == 0) {
            out[ray*3+0] = r0; out[ray*3+1] = r1; out[ray*3+2] = r2;
            out[(long)R * 3 + ray] = dep;
        }
    }
    __syncthreads();

    if (tid < SS) {
        const int m = tid;
        const float w  = sWgt[m];
        const float bw = sBW[m];
        const long o = (long)ray * SS + m;
        const long base = (long)R * 4;
        const long rs = (long)R * SS;
        out[base + o]          = w;
        out[base + rs + o]     = (1.f - bw) * w;
        out[base + 2 * rs + o] = bw * w;
    }
}

extern "C" void kernel_launch(void* const* d_in, const int* in_sizes, int n_in,
                              void* d_out, int out_size)
{
    const float* pts = (const float*)d_in[0];
    const float* dir = (const float*)d_in[1];
    const float* zv  = (const float*)d_in[2];
    const float* tim = (const float*)d_in[3];

    MLPParams st, dy;
    for (int i = 0; i < 5; i++) {
        st.W[i] = (const float*)d_in[4 + 4 * i];
        st.b[i] = (const float*)d_in[5 + 4 * i];
        dy.W[i] = (const float*)d_in[6 + 4 * i];
        dy.b[i] = (const float*)d_in[7 + 4 * i];
    }

    const int R = in_sizes[2] / SS;

    prepass_kernel<<<2 * NCHUNK * 2, 128>>>(st, dy);

    cudaFuncSetAttribute(nerf_main, cudaFuncAttributeMaxDynamicSharedMemorySize, SM_TOTAL);
    nerf_main<<<R, NTHREADS, SM_TOTAL>>>(pts, dir, zv, tim, st, dy, (float*)d_out, R);
}

// round 14
// speedup vs baseline: 2.5293x; 1.5728x over previous
#include <cuda_runtime.h>
#include <cuda_fp16.h>
#include <math.h>
#include <stdint.h>

// ---------------- problem constants ----------------
#define SS        128
#define HID       256
#define NTHREADS  512
#define KC        64               // K per weight chunk (fp16)
#define NCHUNK    14               // per MLP: layer0: 2 (Kpad=128), layers1-3: 4 each
#define ASTRIDE   264              // A plane row stride in fp16 (33*16B: conflict-free ldmatrix)
#define HSTRIDE   260              // fp32 overlay row stride
#define BSTRIDE   72               // B row stride fp16 (9*16B: odd -> conflict-free)
#define BBUF      18432            // one B buffer: 128 rows * 144 B

// ---- shared memory byte offsets ----
#define A_HI      0                              // 128*264*2 = 67584
// per-group double buffers: group*36864 + buf*18432 (single fp16 plane)
#define BUFBASE   67584                          // 2 groups * 36864 = 73728 -> 141312
// layer-3 fp32 overlay (128*260*4 = 133120) spans 67584..200704 (B buffers idle then)
#define SM_W4     200704                         // 256*5*4 = 5120 -> 205824
#define SM_BIAS   205824                         // 1024 -> 206848
#define SM_OUTS   206848                         // 2048 -> 208896 (reused alpha/oma)
#define SM_SIG    208896
#define SM_BW     209408
#define SM_RGB    209920                         // 1536 -> 211456
#define SM_Z      211456
#define SM_WGT    211968
#define SM_TOTAL  212480

// Pre-transposed fp16 weight images per N-half: [mlp][chunk][nhalf][128*64]
__device__ __align__(16) __half g_wimg[2][NCHUNK][2][128 * KC];

struct MLPParams { const float* W[5]; const float* b[5]; };

// ---------------- PTX helpers (all baseline sm_80 ISA) ----------------
__device__ __forceinline__ uint32_t smem_u32(const void* p) {
    uint32_t a;
    asm("{ .reg .u64 t; cvta.to.shared.u64 t, %1; cvt.u32.u64 %0, t; }" : "=r"(a) : "l"(p));
    return a;
}

#define LDSM4(r0, r1, r2, r3, addr) \
    asm volatile("ldmatrix.sync.aligned.m8n8.x4.shared.b16 {%0,%1,%2,%3}, [%4];" \
        : "=r"(r0), "=r"(r1), "=r"(r2), "=r"(r3) : "r"(addr))

#define MMA16816(c, a0, a1, a2, a3, b0, b1) \
    asm volatile("mma.sync.aligned.m16n8k16.row.col.f32.f16.f16.f32 " \
        "{%0,%1,%2,%3}, {%4,%5,%6,%7}, {%8,%9}, {%0,%1,%2,%3};" \
        : "+f"((c)[0]), "+f"((c)[1]), "+f"((c)[2]), "+f"((c)[3]) \
        : "r"(a0), "r"(a1), "r"(a2), "r"(a3), "r"(b0), "r"(b1))

__device__ __forceinline__ void cp16(uint32_t dst, const void* src) {
    asm volatile("cp.async.cg.shared.global [%0], [%1], 16;" :: "r"(dst), "l"(src));
}
#define CP_COMMIT() asm volatile("cp.async.commit_group;" ::: "memory")
#define CP_WAIT1()  asm volatile("cp.async.wait_group 1;" ::: "memory")
#define CP_WAIT0()  asm volatile("cp.async.wait_group 0;" ::: "memory")
#define GBAR(id)    asm volatile("bar.sync %0, 256;" :: "r"(id) : "memory")

__device__ __forceinline__ float sigmoidf_(float x) { return 1.0f / (1.0f + expf(-x)); }

__device__ __forceinline__ uint32_t pack_h2(float v0, float v1) {
    __half2 h = __floats2half2_rn(v0, v1);
    return *reinterpret_cast<uint32_t*>(&h);
}

// ---------------- pre-pass: [N-half=128][Kc=64] fp16 images ----------------
__global__ void prepass_kernel(MLPParams st, MLPParams dy) {
    const int bi  = blockIdx.x;            // 0..55
    const int mlp = bi / (NCHUNK * 2);
    const int rem = bi % (NCHUNK * 2);
    const int c   = rem >> 1;
    const int nh  = rem & 1;
    const int layer = (c < 2) ? 0 : 1 + (c - 2) / 4;
    const int kbase = (c < 2) ? c * KC : ((c - 2) % 4) * KC;
    const float* W = mlp ? dy.W[layer] : st.W[layer];
    const int Kreal = (layer == 0) ? (mlp ? 99 : 90) : HID;

    __half* outH = g_wimg[mlp][c][nh];
    const int n = threadIdx.x;             // 0..127 local N
    const int ng = nh * 128 + n;           // global N
    for (int k = 0; k < KC; k++) {
        const int kg = kbase + k;
        const float w = (kg < Kreal) ? __ldg(W + (size_t)kg * HID + ng) : 0.f;
        outH[n * KC + k] = __float2half_rn(w);
    }
}

// ---- GEMM chunk: warp tile 64(M) x 32(N), Kc=64, single fp16 W plane ----
// acc index: ms*4 + nf  (ms 0..3 = 16-row block, nf 0..3 = n8 fragment)
__device__ __forceinline__ void gemm_chunk(uint32_t aBase, uint32_t bB, float acc[16][4]) {
    uint32_t b[2][8];
#pragma unroll
    for (int ns = 0; ns < 2; ns++)
        LDSM4(b[0][ns*4+0], b[0][ns*4+1], b[0][ns*4+2], b[0][ns*4+3],
              bB + ns * (16 * BSTRIDE * 2));
#pragma unroll
    for (int ks = 0; ks < 4; ks++) {
        const int cur = ks & 1, nxt = cur ^ 1;
        if (ks < 3) {
            const uint32_t nbk = bB + (ks + 1) * 32;
#pragma unroll
            for (int ns = 0; ns < 2; ns++)
                LDSM4(b[nxt][ns*4+0], b[nxt][ns*4+1], b[nxt][ns*4+2], b[nxt][ns*4+3],
                      nbk + ns * (16 * BSTRIDE * 2));
        }
        uint32_t a[16];
#pragma unroll
        for (int ms = 0; ms < 4; ms++)
            LDSM4(a[ms*4+0], a[ms*4+1], a[ms*4+2], a[ms*4+3],
                  aBase + ks * 32 + ms * (16 * ASTRIDE * 2));
#pragma unroll
        for (int ms = 0; ms < 4; ms++) {
#pragma unroll
            for (int ns = 0; ns < 2; ns++) {
                float* c0 = acc[ms * 4 + ns * 2];
                float* c1 = acc[ms * 4 + ns * 2 + 1];
                MMA16816(c0, a[ms*4+0], a[ms*4+1], a[ms*4+2], a[ms*4+3],
                         b[cur][ns*4+0], b[cur][ns*4+1]);
                MMA16816(c1, a[ms*4+0], a[ms*4+1], a[ms*4+2], a[ms*4+3],
                         b[cur][ns*4+2], b[cur][ns*4+3]);
            }
        }
    }
}

// ---------------- main kernel ----------------
__global__ void __launch_bounds__(NTHREADS, 1)
nerf_main(const float* __restrict__ pts, const float* __restrict__ dir,
          const float* __restrict__ zv,  const float* __restrict__ tim,
          MLPParams st, MLPParams dy, float* __restrict__ out, int R)
{
    extern __shared__ char sm[];
    const uint32_t sbase = smem_u32(sm);

    const int tid  = threadIdx.x;
    const int wid  = tid >> 5;
    const int lane = tid & 31;
    const int ray  = blockIdx.x;

    const int group = wid >> 3;          // 0,1 -> N cols [0..127], [128..255]
    const int gw    = wid & 7;
    const int mi    = gw >> 2;           // 0..1 -> rows 64*mi
    const int njg   = gw & 3;            // 0..3 -> cols group*128 + njg*32
    const int gtid  = tid & 255;
    const uint32_t myBufBase = sbase + BUFBASE + (uint32_t)group * (2 * BBUF);

    float* sZ    = (float*)(sm + SM_Z);
    float* sWgt  = (float*)(sm + SM_WGT);
    float* sSig  = (float*)(sm + SM_SIG);
    float* sBW   = (float*)(sm + SM_BW);
    float* sRgb  = (float*)(sm + SM_RGB);
    float* sOutS = (float*)(sm + SM_OUTS);
    float* sBias = (float*)(sm + SM_BIAS);
    float* sW4f  = (float*)(sm + SM_W4);
    float* sHf   = (float*)(sm + BUFBASE);   // fp32 overlay (layer-3 out), stride HSTRIDE

    if (tid < SS) sZ[tid] = zv[(long)ray * SS + tid];

    // per-thread ldmatrix address components
    const int r8 = lane & 7, g = lane >> 3;
    const uint32_t aRow = (uint32_t)(64 * mi + (g & 1) * 8 + r8);
    const uint32_t aColOff = (uint32_t)((g >> 1) * 8);
    const uint32_t aHiBase = sbase + A_HI + (aRow * ASTRIDE + aColOff) * 2;
    const uint32_t bRow = (uint32_t)(njg * 32 + (g >> 1) * 8 + r8);   // local in group image
    const uint32_t bOff = (bRow * BSTRIDE + (g & 1) * 8) * 2;

    const int rowBase = 64 * mi + (lane >> 2);       // + 16*ms, +8 for c[2..3]
    const int colBase = group * 128 + njg * 32 + 2 * (lane & 3);   // + 8*nf

    for (int mlp = 0; mlp < 2; mlp++) {
        const float* const* Wp = mlp ? dy.W : st.W;
        const float* const* Bp = mlp ? dy.b : st.b;
        const int n4 = mlp ? 5 : 4;

        CP_WAIT0();
        __syncthreads();       // B-buffer region (incl. sHf overlay) free for reuse

        // ---- encode directly into fp16 A plane, 4-way warp-uniform split ----
        {
            const int m = tid & 127;
            const int q = tid >> 7;
            const long base = (long)ray * SS + m;
            char* arow = sm + A_HI + (size_t)m * (ASTRIDE * 2);
#define STH(col, v) (*(__half*)(arow + (col) * 2) = __float2half_rn(v))
            if (q == 0) {
                const float p0 = pts[base*3+0], p1 = pts[base*3+1], p2 = pts[base*3+2];
                STH(0, p0); STH(1, p1); STH(2, p2);
                float f = 1.f;
#pragma unroll
                for (int l = 0; l < 5; l++) {
                    float s0,c0,s1,c1,s2,c2;
                    sincosf(f*p0,&s0,&c0); sincosf(f*p1,&s1,&c1); sincosf(f*p2,&s2,&c2);
                    const int o = 3 + 6*l;
                    STH(o,s0); STH(o+1,s1); STH(o+2,s2);
                    STH(o+3,c0); STH(o+4,c1); STH(o+5,c2);
                    f *= 2.f;
                }
            } else if (q == 1) {
                const float p0 = pts[base*3+0], p1 = pts[base*3+1], p2 = pts[base*3+2];
                float f = 32.f;
#pragma unroll
                for (int l = 0; l < 5; l++) {
                    float s0,c0,s1,c1,s2,c2;
                    sincosf(f*p0,&s0,&c0); sincosf(f*p1,&s1,&c1); sincosf(f*p2,&s2,&c2);
                    const int o = 33 + 6*l;
                    STH(o,s0); STH(o+1,s1); STH(o+2,s2);
                    STH(o+3,c0); STH(o+4,c1); STH(o+5,c2);
                    f *= 2.f;
                }
            } else if (q == 2) {
                const float d0 = dir[base*3+0], d1 = dir[base*3+1], d2 = dir[base*3+2];
                STH(63, d0); STH(64, d1); STH(65, d2);
                float f = 1.f;
#pragma unroll
                for (int l = 0; l < 4; l++) {
                    float s0,c0,s1,c1,s2,c2;
                    sincosf(f*d0,&s0,&c0); sincosf(f*d1,&s1,&c1); sincosf(f*d2,&s2,&c2);
                    const int o = 66 + 6*l;
                    STH(o,s0); STH(o+1,s1); STH(o+2,s2);
                    STH(o+3,c0); STH(o+4,c1); STH(o+5,c2);
                    f *= 2.f;
                }
            } else {
                const float t = tim[base];
                STH(90, t);
                float f = 1.f;
#pragma unroll
                for (int l = 0; l < 4; l++) {
                    float s, c; sincosf(f*t, &s, &c);
                    STH(91 + 2*l, s); STH(92 + 2*l, c);
                    f *= 2.f;
                }
#pragma unroll
                for (int col = 99; col < 128; col++) STH(col, 0.f);
            }
#undef STH
        }
        __syncthreads();

        // ---- per-group prefetch of chunks 0,1 (1024 x 16B per chunk) ----
        int cg = 0;
        for (int pc = 0; pc < 2; pc++) {
            const char* src = (const char*)g_wimg[mlp][pc][group];
            const uint32_t dstB = myBufBase + (uint32_t)pc * BBUF;
#pragma unroll
            for (int i = 0; i < 4; i++) {
                const int idx = gtid + i * 256;                  // 0..1023
                const uint32_t d = dstB + (uint32_t)(idx >> 3) * (BSTRIDE * 2) + (idx & 7) * 16;
                cp16(d, src + idx * 16);
            }
            CP_COMMIT();
        }

        for (int layer = 0; layer < 4; layer++) {
            for (int i = tid; i < HID; i += NTHREADS) sBias[i] = __ldg(Bp[layer] + i);
            if (layer == 3)
                for (int i = tid; i < HID * n4; i += NTHREADS) sW4f[i] = __ldg(Wp[4] + i);

            float acc[16][4];
#pragma unroll
            for (int a = 0; a < 16; a++)
#pragma unroll
                for (int q = 0; q < 4; q++) acc[a][q] = 0.f;

            const int nch = (layer == 0) ? 2 : 4;
            for (int c = 0; c < nch; c++) {
                CP_WAIT1();                        // group's chunk cg resident
                GBAR(1 + group);
                const uint32_t bB = myBufBase + (uint32_t)(cg & 1) * BBUF + bOff;
                gemm_chunk(aHiBase + c * (KC * 2), bB, acc);
                GBAR(1 + group);                   // group done reading buf (cg&1)
                if (cg + 2 < NCHUNK) {
                    const char* src = (const char*)g_wimg[mlp][cg + 2][group];
                    const uint32_t dstB = myBufBase + (uint32_t)(cg & 1) * BBUF;
#pragma unroll
                    for (int i = 0; i < 4; i++) {
                        const int idx = gtid + i * 256;
                        const uint32_t d = dstB + (uint32_t)(idx >> 3) * (BSTRIDE * 2) + (idx & 7) * 16;
                        cp16(d, src + idx * 16);
                    }
                }
                CP_COMMIT();                       // uniform group count
                cg++;
            }

            __syncthreads();   // both groups finished MMAs before in-place A / overlay write

            if (layer < 3) {
                uint32_t* aH = (uint32_t*)(sm + A_HI);
#pragma unroll
                for (int idx = 0; idx < 16; idx++) {
                    const int ms = idx >> 2, nf = idx & 3;
                    const int row = rowBase + 16 * ms;
                    const int col = colBase + 8 * nf;
                    const float b0 = sBias[col], b1 = sBias[col + 1];
                    const float h00 = fmaxf(acc[idx][0] + b0, 0.f);
                    const float h01 = fmaxf(acc[idx][1] + b1, 0.f);
                    const float h10 = fmaxf(acc[idx][2] + b0, 0.f);
                    const float h11 = fmaxf(acc[idx][3] + b1, 0.f);
                    aH[row * (ASTRIDE/2) + (col >> 1)]       = pack_h2(h00, h01);
                    aH[(row + 8) * (ASTRIDE/2) + (col >> 1)] = pack_h2(h10, h11);
                }
            } else {
                // fp32 relu output into overlay (all chunk data consumed)
#pragma unroll
                for (int idx = 0; idx < 16; idx++) {
                    const int ms = idx >> 2, nf = idx & 3;
                    const int row = rowBase + 16 * ms;
                    const int col = colBase + 8 * nf;
                    const float b0 = sBias[col], b1 = sBias[col + 1];
                    sHf[row * HSTRIDE + col]           = fmaxf(acc[idx][0] + b0, 0.f);
                    sHf[row * HSTRIDE + col + 1]       = fmaxf(acc[idx][1] + b1, 0.f);
                    sHf[(row + 8) * HSTRIDE + col]     = fmaxf(acc[idx][2] + b0, 0.f);
                    sHf[(row + 8) * HSTRIDE + col + 1] = fmaxf(acc[idx][3] + b1, 0.f);
                }
            }
            __syncthreads();
        }

        // ---- final 256 -> n4 dot: 2 threads per sample, shfl combine ----
        if (tid < 2 * SS) {
            const int m = tid >> 1, half = tid & 1;
            float o5[5];
            const float* b4 = Bp[4];
#pragma unroll
            for (int j = 0; j < 5; j++) o5[j] = (half == 0 && j < n4) ? __ldg(b4 + j) : 0.f;
            const float* arow = sHf + m * HSTRIDE + half * 128;
            for (int k = 0; k < 128; k += 4) {
                const float4 a = *reinterpret_cast<const float4*>(arow + k);
                const int kw = half * 128 + k;
#pragma unroll
                for (int kk = 0; kk < 4; kk++) {
                    const float av = (kk == 0) ? a.x : (kk == 1) ? a.y : (kk == 2) ? a.z : a.w;
#pragma unroll
                    for (int j = 0; j < 5; j++)
                        if (j < n4) o5[j] += av * sW4f[(kw + kk) * n4 + j];
                }
            }
#pragma unroll
            for (int j = 0; j < 5; j++) o5[j] += __shfl_xor_sync(0xffffffffu, o5[j], 1);
            if (half == 0) {
                if (mlp == 0) {
                    sOutS[m*4+0] = o5[0]; sOutS[m*4+1] = o5[1];
                    sOutS[m*4+2] = o5[2]; sOutS[m*4+3] = o5[3];
                } else {
                    const float bw = sigmoidf_(o5[4]);
                    sSig[m] = (1.f - bw) * sOutS[m*4+0] + bw * o5[0];
                    sBW[m]  = bw;
#pragma unroll
                    for (int cc = 0; cc < 3; cc++) {
                        const float rs = sigmoidf_(sOutS[m*4+1+cc]);
                        const float rd = sigmoidf_(o5[1+cc]);
                        sRgb[m*3+cc] = (1.f - bw) * rs + bw * rd;
                    }
                }
            }
        }
        __syncthreads();
    }

    // ---- parallel alpha, then warp-0 prefix-product scan + reductions ----
    float* sAlpha = sOutS;            // reuse (sOutS dead now)
    float* sOma   = sOutS + SS;
    if (tid < SS) {
        const float z = sZ[tid];
        const float delta = (tid < SS - 1) ? (sZ[tid + 1] - z) : 1e10f;
        const float alpha = 1.f - expf(-sSig[tid] * delta);
        sAlpha[tid] = alpha;
        sOma[tid]   = 1.f - alpha + 1e-10f;
    }
    __syncthreads();
    if (wid == 0) {
        float a[4], o[4], zr[4], rg[4][3];
#pragma unroll
        for (int j = 0; j < 4; j++) {
            const int m = 4 * lane + j;
            a[j] = sAlpha[m]; o[j] = sOma[m]; zr[j] = sZ[m];
            rg[j][0] = sRgb[m*3+0]; rg[j][1] = sRgb[m*3+1]; rg[j][2] = sRgb[m*3+2];
        }
        float run = o[0] * o[1] * o[2] * o[3];
#pragma unroll
        for (int d = 1; d < 32; d <<= 1) {
            const float v = __shfl_up_sync(0xffffffffu, run, d);
            if (lane >= d) run *= v;
        }
        float T = __shfl_up_sync(0xffffffffu, run, 1);
        if (lane == 0) T = 1.f;
        float r0 = 0.f, r1 = 0.f, r2 = 0.f, dep = 0.f;
#pragma unroll
        for (int j = 0; j < 4; j++) {
            const float w = a[j] * T;
            sWgt[4 * lane + j] = w;
            r0 += w * rg[j][0]; r1 += w * rg[j][1]; r2 += w * rg[j][2];
            dep += w * zr[j];
            T *= o[j];
        }
#pragma unroll
        for (int d = 16; d > 0; d >>= 1) {
            r0  += __shfl_xor_sync(0xffffffffu, r0, d);
            r1  += __shfl_xor_sync(0xffffffffu, r1, d);
            r2  += __shfl_xor_sync(0xffffffffu, r2, d);
            dep += __shfl_xor_sync(0xffffffffu, dep, d);
        }
        if (lane == 0) {
            out[ray*3+0] = r0; out[ray*3+1] = r1; out[ray*3+2] = r2;
            out[(long)R * 3 + ray] = dep;
        }
    }
    __syncthreads();

    if (tid < SS) {
        const int m = tid;
        const float w  = sWgt[m];
        const float bw = sBW[m];
        const long o = (long)ray * SS + m;
        const long base = (long)R * 4;
        const long rs = (long)R * SS;
        out[base + o]          = w;
        out[base + rs + o]     = (1.f - bw) * w;
        out[base + 2 * rs + o] = bw * w;
    }
}

extern "C" void kernel_launch(void* const* d_in, const int* in_sizes, int n_in,
                              void* d_out, int out_size)
{
    const float* pts = (const float*)d_in[0];
    const float* dir = (const float*)d_in[1];
    const float* zv  = (const float*)d_in[2];
    const float* tim = (const float*)d_in[3];

    MLPParams st, dy;
    for (int i = 0; i < 5; i++) {
        st.W[i] = (const float*)d_in[4 + 4 * i];
        st.b[i] = (const float*)d_in[5 + 4 * i];
        dy.W[i] = (const float*)d_in[6 + 4 * i];
        dy.b[i] = (const float*)d_in[7 + 4 * i];
    }

    const int R = in_sizes[2] / SS;

    prepass_kernel<<<2 * NCHUNK * 2, 128>>>(st, dy);

    cudaFuncSetAttribute(nerf_main, cudaFuncAttributeMaxDynamicSharedMemorySize, SM_TOTAL);
    nerf_main<<<R, NTHREADS, SM_TOTAL>>>(pts, dir, zv, tim, st, dy, (float*)d_out, R);
}

// round 15
// speedup vs baseline: 2.6399x; 1.0437x over previous
#include <cuda_runtime.h>
#include <cuda_fp16.h>
#include <math.h>
#include <stdint.h>

// ---------------- problem constants ----------------
#define SS        128
#define HID       256
#define NTHREADS  512
#define KC        64               // K per weight chunk (fp16)
#define NCHUNK    14               // per MLP: layer0: 2 (Kpad=128), layers1-3: 4 each
#define ASTRIDE   264              // A plane row stride in fp16 (33*16B: conflict-free ldmatrix)
#define BSTRIDE   72               // B row stride fp16 (9*16B: odd -> conflict-free)
#define BBUF      18432            // one B buffer: 128 rows * 144 B
#define PLANE     67584            // one A plane: 128*264*2

// ---- shared memory byte offsets ----
#define A_P0      0                              // plane 0
#define A_P1      67584                          // plane 1
#define BUFBASE   135168                         // + group*36864 + buf*18432 -> 208896
#define SM_W4     208896                         // 256*5*4 = 5120 -> 214016
#define SM_OUTS   214016                         // 2048 -> 216064 (reused alpha/oma)
#define SM_SIG    216064
#define SM_BW     216576
#define SM_RGB    217088                         // 1536 -> 218624
#define SM_Z      218624
#define SM_WGT    219136
#define SM_TOTAL  219648

// Pre-transposed fp16 weight images per N-half: [mlp][chunk][nhalf][128*64]
__device__ __align__(16) __half g_wimg[2][NCHUNK][2][128 * KC];

struct MLPParams { const float* W[5]; const float* b[5]; };

// ---------------- PTX helpers (all baseline sm_80 ISA) ----------------
__device__ __forceinline__ uint32_t smem_u32(const void* p) {
    uint32_t a;
    asm("{ .reg .u64 t; cvta.to.shared.u64 t, %1; cvt.u32.u64 %0, t; }" : "=r"(a) : "l"(p));
    return a;
}

#define LDSM4(r0, r1, r2, r3, addr) \
    asm volatile("ldmatrix.sync.aligned.m8n8.x4.shared.b16 {%0,%1,%2,%3}, [%4];" \
        : "=r"(r0), "=r"(r1), "=r"(r2), "=r"(r3) : "r"(addr))

#define MMA16816(c, a0, a1, a2, a3, b0, b1) \
    asm volatile("mma.sync.aligned.m16n8k16.row.col.f32.f16.f16.f32 " \
        "{%0,%1,%2,%3}, {%4,%5,%6,%7}, {%8,%9}, {%0,%1,%2,%3};" \
        : "+f"((c)[0]), "+f"((c)[1]), "+f"((c)[2]), "+f"((c)[3]) \
        : "r"(a0), "r"(a1), "r"(a2), "r"(a3), "r"(b0), "r"(b1))

__device__ __forceinline__ void cp16(uint32_t dst, const void* src) {
    asm volatile("cp.async.cg.shared.global [%0], [%1], 16;" :: "r"(dst), "l"(src));
}
#define CP_COMMIT() asm volatile("cp.async.commit_group;" ::: "memory")
#define CP_WAIT1()  asm volatile("cp.async.wait_group 1;" ::: "memory")
#define CP_WAIT0()  asm volatile("cp.async.wait_group 0;" ::: "memory")
#define GBAR(id)    asm volatile("bar.sync %0, 256;" :: "r"(id) : "memory")

__device__ __forceinline__ float sigmoidf_(float x) { return 1.0f / (1.0f + expf(-x)); }

__device__ __forceinline__ uint32_t pack_h2(float v0, float v1) {
    __half2 h = __floats2half2_rn(v0, v1);
    return *reinterpret_cast<uint32_t*>(&h);
}
__device__ __forceinline__ float2 h2f(uint32_t u) {
    __half2 h = *reinterpret_cast<__half2*>(&u);
    return __half22float2(h);
}

// ---------------- pre-pass: [N-half=128][Kc=64] fp16 images ----------------
__global__ void prepass_kernel(MLPParams st, MLPParams dy) {
    const int bi  = blockIdx.x;            // 0..55
    const int mlp = bi / (NCHUNK * 2);
    const int rem = bi % (NCHUNK * 2);
    const int c   = rem >> 1;
    const int nh  = rem & 1;
    const int layer = (c < 2) ? 0 : 1 + (c - 2) / 4;
    const int kbase = (c < 2) ? c * KC : ((c - 2) % 4) * KC;
    const float* W = mlp ? dy.W[layer] : st.W[layer];
    const int Kreal = (layer == 0) ? (mlp ? 99 : 90) : HID;

    __half* outH = g_wimg[mlp][c][nh];
    const int n = threadIdx.x;             // 0..127 local N
    const int ng = nh * 128 + n;           // global N
    for (int k = 0; k < KC; k++) {
        const int kg = kbase + k;
        const float w = (kg < Kreal) ? __ldg(W + (size_t)kg * HID + ng) : 0.f;
        outH[n * KC + k] = __float2half_rn(w);
    }
}

// ---- GEMM chunk: warp tile 64(M) x 32(N), Kc=64, LDS/MMA interleaved ----
// acc index: ms*4 + ns*2 + {0,1}
__device__ __forceinline__ void gemm_chunk(uint32_t aBase, uint32_t bB, float acc[16][4]) {
    uint32_t a[16], b[2][8];
    // prologue: a(ks=0) all ms, b(ks=0)
#pragma unroll
    for (int ms = 0; ms < 4; ms++)
        LDSM4(a[ms*4+0], a[ms*4+1], a[ms*4+2], a[ms*4+3],
              aBase + ms * (16 * ASTRIDE * 2));
#pragma unroll
    for (int ns = 0; ns < 2; ns++)
        LDSM4(b[0][ns*4+0], b[0][ns*4+1], b[0][ns*4+2], b[0][ns*4+3],
              bB + ns * (16 * BSTRIDE * 2));
#pragma unroll
    for (int ks = 0; ks < 4; ks++) {
        const int cur = ks & 1, nxt = cur ^ 1;
        if (ks < 3) {
            const uint32_t nbk = bB + (ks + 1) * 32;
#pragma unroll
            for (int ns = 0; ns < 2; ns++)
                LDSM4(b[nxt][ns*4+0], b[nxt][ns*4+1], b[nxt][ns*4+2], b[nxt][ns*4+3],
                      nbk + ns * (16 * BSTRIDE * 2));
        }
#pragma unroll
        for (int ms = 0; ms < 4; ms++) {
            // 4 MMAs consuming a[ms] (ks)
            MMA16816(acc[ms*4+0], a[ms*4+0], a[ms*4+1], a[ms*4+2], a[ms*4+3],
                     b[cur][0], b[cur][1]);
            MMA16816(acc[ms*4+1], a[ms*4+0], a[ms*4+1], a[ms*4+2], a[ms*4+3],
                     b[cur][2], b[cur][3]);
            MMA16816(acc[ms*4+2], a[ms*4+0], a[ms*4+1], a[ms*4+2], a[ms*4+3],
                     b[cur][4], b[cur][5]);
            MMA16816(acc[ms*4+3], a[ms*4+0], a[ms*4+1], a[ms*4+2], a[ms*4+3],
                     b[cur][6], b[cur][7]);
            // immediately reload a[ms] with ks+1 (independent chain per ms)
            if (ks < 3)
                LDSM4(a[ms*4+0], a[ms*4+1], a[ms*4+2], a[ms*4+3],
                      aBase + (ks + 1) * 32 + ms * (16 * ASTRIDE * 2));
        }
    }
}

// ---------------- main kernel ----------------
__global__ void __launch_bounds__(NTHREADS, 1)
nerf_main(const float* __restrict__ pts, const float* __restrict__ dir,
          const float* __restrict__ zv,  const float* __restrict__ tim,
          MLPParams st, MLPParams dy, float* __restrict__ out, int R)
{
    extern __shared__ char sm[];
    const uint32_t sbase = smem_u32(sm);

    const int tid  = threadIdx.x;
    const int wid  = tid >> 5;
    const int lane = tid & 31;
    const int ray  = blockIdx.x;

    const int group = wid >> 3;          // 0,1 -> N cols [0..127], [128..255]
    const int gw    = wid & 7;
    const int mi    = gw >> 2;           // 0..1 -> rows 64*mi
    const int njg   = gw & 3;            // 0..3 -> cols group*128 + njg*32
    const int gtid  = tid & 255;
    const uint32_t myBufBase = sbase + BUFBASE + (uint32_t)group * (2 * BBUF);

    float* sZ    = (float*)(sm + SM_Z);
    float* sWgt  = (float*)(sm + SM_WGT);
    float* sSig  = (float*)(sm + SM_SIG);
    float* sBW   = (float*)(sm + SM_BW);
    float* sRgb  = (float*)(sm + SM_RGB);
    float* sOutS = (float*)(sm + SM_OUTS);
    float* sW4f  = (float*)(sm + SM_W4);

    if (tid < SS) sZ[tid] = zv[(long)ray * SS + tid];

    // per-thread ldmatrix address components
    const int r8 = lane & 7, g = lane >> 3;
    const uint32_t aRow = (uint32_t)(64 * mi + (g & 1) * 8 + r8);
    const uint32_t aColOff = (uint32_t)((g >> 1) * 8);
    const uint32_t aOffBase = (aRow * ASTRIDE + aColOff) * 2;
    const uint32_t bRow = (uint32_t)(njg * 32 + (g >> 1) * 8 + r8);   // local in group image
    const uint32_t bOff = (bRow * BSTRIDE + (g & 1) * 8) * 2;

    const int rowBase = 64 * mi + (lane >> 2);       // + 16*ms, +8 for c[2..3]
    const int colBase = group * 128 + njg * 32 + 2 * (lane & 3);   // + 8*nf

    for (int mlp = 0; mlp < 2; mlp++) {
        const float* const* Wp = mlp ? dy.W : st.W;
        const float* const* Bp = mlp ? dy.b : st.b;
        const int n4 = mlp ? 5 : 4;

        CP_WAIT0();
        __syncthreads();       // prior-phase smem reuse safe

        // ---- encode directly into fp16 plane 0, 4-way warp-uniform split ----
        {
            const int m = tid & 127;
            const int q = tid >> 7;
            const long base = (long)ray * SS + m;
            char* arow = sm + A_P0 + (size_t)m * (ASTRIDE * 2);
#define STH(col, v) (*(__half*)(arow + (col) * 2) = __float2half_rn(v))
            if (q == 0) {
                const float p0 = pts[base*3+0], p1 = pts[base*3+1], p2 = pts[base*3+2];
                STH(0, p0); STH(1, p1); STH(2, p2);
                float f = 1.f;
#pragma unroll
                for (int l = 0; l < 5; l++) {
                    float s0,c0,s1,c1,s2,c2;
                    sincosf(f*p0,&s0,&c0); sincosf(f*p1,&s1,&c1); sincosf(f*p2,&s2,&c2);
                    const int o = 3 + 6*l;
                    STH(o,s0); STH(o+1,s1); STH(o+2,s2);
                    STH(o+3,c0); STH(o+4,c1); STH(o+5,c2);
                    f *= 2.f;
                }
            } else if (q == 1) {
                const float p0 = pts[base*3+0], p1 = pts[base*3+1], p2 = pts[base*3+2];
                float f = 32.f;
#pragma unroll
                for (int l = 0; l < 5; l++) {
                    float s0,c0,s1,c1,s2,c2;
                    sincosf(f*p0,&s0,&c0); sincosf(f*p1,&s1,&c1); sincosf(f*p2,&s2,&c2);
                    const int o = 33 + 6*l;
                    STH(o,s0); STH(o+1,s1); STH(o+2,s2);
                    STH(o+3,c0); STH(o+4,c1); STH(o+5,c2);
                    f *= 2.f;
                }
            } else if (q == 2) {
                const float d0 = dir[base*3+0], d1 = dir[base*3+1], d2 = dir[base*3+2];
                STH(63, d0); STH(64, d1); STH(65, d2);
                float f = 1.f;
#pragma unroll
                for (int l = 0; l < 4; l++) {
                    float s0,c0,s1,c1,s2,c2;
                    sincosf(f*d0,&s0,&c0); sincosf(f*d1,&s1,&c1); sincosf(f*d2,&s2,&c2);
                    const int o = 66 + 6*l;
                    STH(o,s0); STH(o+1,s1); STH(o+2,s2);
                    STH(o+3,c0); STH(o+4,c1); STH(o+5,c2);
                    f *= 2.f;
                }
            } else {
                const float t = tim[base];
                STH(90, t);
                float f = 1.f;
#pragma unroll
                for (int l = 0; l < 4; l++) {
                    float s, c; sincosf(f*t, &s, &c);
                    STH(91 + 2*l, s); STH(92 + 2*l, c);
                    f *= 2.f;
                }
#pragma unroll
                for (int col = 99; col < 128; col++) STH(col, 0.f);
            }
#undef STH
        }
        __syncthreads();

        // ---- per-group prefetch of chunks 0,1 (1024 x 16B per chunk) ----
        int cg = 0;
        for (int pc = 0; pc < 2; pc++) {
            const char* src = (const char*)g_wimg[mlp][pc][group];
            const uint32_t dstB = myBufBase + (uint32_t)pc * BBUF;
#pragma unroll
            for (int i = 0; i < 4; i++) {
                const int idx = gtid + i * 256;                  // 0..1023
                const uint32_t d = dstB + (uint32_t)(idx >> 3) * (BSTRIDE * 2) + (idx & 7) * 16;
                cp16(d, src + idx * 16);
            }
            CP_COMMIT();
        }

        for (int layer = 0; layer < 4; layer++) {
            const uint32_t rPlane = sbase + (uint32_t)(layer & 1) * PLANE;   // read plane
            if (layer == 3)
                for (int i = tid; i < HID * n4; i += NTHREADS) sW4f[i] = __ldg(Wp[4] + i);

            float acc[16][4];
#pragma unroll
            for (int a = 0; a < 16; a++)
#pragma unroll
                for (int q = 0; q < 4; q++) acc[a][q] = 0.f;

            const int nch = (layer == 0) ? 2 : 4;
            for (int c = 0; c < nch; c++) {
                CP_WAIT1();                        // group's chunk cg resident
                GBAR(1 + group);                   // visibility of group's cp.async
                const uint32_t bB = myBufBase + (uint32_t)(cg & 1) * BBUF + bOff;
                gemm_chunk(rPlane + aOffBase + c * (KC * 2), bB, acc);
                GBAR(1 + group);                   // group done reading buf (cg&1)
                if (cg + 2 < NCHUNK) {
                    const char* src = (const char*)g_wimg[mlp][cg + 2][group];
                    const uint32_t dstB = myBufBase + (uint32_t)(cg & 1) * BBUF;
#pragma unroll
                    for (int i = 0; i < 4; i++) {
                        const int idx = gtid + i * 256;
                        const uint32_t d = dstB + (uint32_t)(idx >> 3) * (BSTRIDE * 2) + (idx & 7) * 16;
                        cp16(d, src + idx * 16);
                    }
                }
                CP_COMMIT();                       // uniform group count
                cg++;
            }

            // ---- epilogue: write relu(acc+bias) as fp16 into the PONG plane
            //      (no barrier needed: write plane != read plane) ----
            {
                uint32_t* aW = (uint32_t*)(sm + (((layer & 1) ^ 1) ? A_P1 : A_P0));
                const float* bb = Bp[layer];
#pragma unroll
                for (int idx = 0; idx < 16; idx++) {
                    const int ms = idx >> 2, nf = idx & 3;
                    const int row = rowBase + 16 * ms;
                    const int col = colBase + 8 * nf;
                    const float2 bv = __ldg((const float2*)(bb + col));
                    const float h00 = fmaxf(acc[idx][0] + bv.x, 0.f);
                    const float h01 = fmaxf(acc[idx][1] + bv.y, 0.f);
                    const float h10 = fmaxf(acc[idx][2] + bv.x, 0.f);
                    const float h11 = fmaxf(acc[idx][3] + bv.y, 0.f);
                    aW[row * (ASTRIDE/2) + (col >> 1)]       = pack_h2(h00, h01);
                    aW[(row + 8) * (ASTRIDE/2) + (col >> 1)] = pack_h2(h10, h11);
                }
            }
            __syncthreads();   // all of next layer's A written before anyone reads it
        }

        // ---- final 256 -> n4 dot: 2 threads per sample (fp16 hidden in plane 0) ----
        if (tid < 2 * SS) {
            const int m = tid >> 1, half = tid & 1;
            float o5[5];
            const float* b4 = Bp[4];
#pragma unroll
            for (int j = 0; j < 5; j++) o5[j] = (half == 0 && j < n4) ? __ldg(b4 + j) : 0.f;
            const char* arow = sm + A_P0 + (size_t)(m * ASTRIDE + half * 128) * 2;
            for (int kk = 0; kk < 16; kk++) {
                const uint4 v = *(const uint4*)(arow + kk * 16);
                const float2 f0 = h2f(v.x), f1 = h2f(v.y), f2 = h2f(v.z), f3 = h2f(v.w);
                const float* w = sW4f + (half * 128 + kk * 8) * n4;
#pragma unroll
                for (int j = 0; j < 5; j++) {
                    if (j < n4) {
                        o5[j] += f0.x * w[0*n4+j] + f0.y * w[1*n4+j]
                               + f1.x * w[2*n4+j] + f1.y * w[3*n4+j]
                               + f2.x * w[4*n4+j] + f2.y * w[5*n4+j]
                               + f3.x * w[6*n4+j] + f3.y * w[7*n4+j];
                    }
                }
            }
#pragma unroll
            for (int j = 0; j < 5; j++) o5[j] += __shfl_xor_sync(0xffffffffu, o5[j], 1);
            if (half == 0) {
                if (mlp == 0) {
                    sOutS[m*4+0] = o5[0]; sOutS[m*4+1] = o5[1];
                    sOutS[m*4+2] = o5[2]; sOutS[m*4+3] = o5[3];
                } else {
                    const float bw = sigmoidf_(o5[4]);
                    sSig[m] = (1.f - bw) * sOutS[m*4+0] + bw * o5[0];
                    sBW[m]  = bw;
#pragma unroll
                    for (int cc = 0; cc < 3; cc++) {
                        const float rs = sigmoidf_(sOutS[m*4+1+cc]);
                        const float rd = sigmoidf_(o5[1+cc]);
                        sRgb[m*3+cc] = (1.f - bw) * rs + bw * rd;
                    }
                }
            }
        }
        __syncthreads();
    }

    // ---- parallel alpha, then warp-0 prefix-product scan + reductions ----
    float* sAlpha = sOutS;            // reuse (sOutS dead now)
    float* sOma   = sOutS + SS;
    if (tid < SS) {
        const float z = sZ[tid];
        const float delta = (tid < SS - 1) ? (sZ[tid + 1] - z) : 1e10f;
        const float alpha = 1.f - expf(-sSig[tid] * delta);
        sAlpha[tid] = alpha;
        sOma[tid]   = 1.f - alpha + 1e-10f;
    }
    __syncthreads();
    if (wid == 0) {
        float a[4], o[4], zr[4], rg[4][3];
#pragma unroll
        for (int j = 0; j < 4; j++) {
            const int m = 4 * lane + j;
            a[j] = sAlpha[m]; o[j] = sOma[m]; zr[j] = sZ[m];
            rg[j][0] = sRgb[m*3+0]; rg[j][1] = sRgb[m*3+1]; rg[j][2] = sRgb[m*3+2];
        }
        float run = o[0] * o[1] * o[2] * o[3];
#pragma unroll
        for (int d = 1; d < 32; d <<= 1) {
            const float v = __shfl_up_sync(0xffffffffu, run, d);
            if (lane >= d) run *= v;
        }
        float T = __shfl_up_sync(0xffffffffu, run, 1);
        if (lane == 0) T = 1.f;
        float r0 = 0.f, r1 = 0.f, r2 = 0.f, dep = 0.f;
#pragma unroll
        for (int j = 0; j < 4; j++) {
            const float w = a[j] * T;
            sWgt[4 * lane + j] = w;
            r0 += w * rg[j][0]; r1 += w * rg[j][1]; r2 += w * rg[j][2];
            dep += w * zr[j];
            T *= o[j];
        }
#pragma unroll
        for (int d = 16; d > 0; d >>= 1) {
            r0  += __shfl_xor_sync(0xffffffffu, r0, d);
            r1  += __shfl_xor_sync(0xffffffffu, r1, d);
            r2  += __shfl_xor_sync(0xffffffffu, r2, d);
            dep += __shfl_xor_sync(0xffffffffu, dep, d);
        }
        if (lane == 0) {
            out[ray*3+0] = r0; out[ray*3+1] = r1; out[ray*3+2] = r2;
            out[(long)R * 3 + ray] = dep;
        }
    }
    __syncthreads();

    if (tid < SS) {
        const int m = tid;
        const float w  = sWgt[m];
        const float bw = sBW[m];
        const long o = (long)ray * SS + m;
        const long base = (long)R * 4;
        const long rs = (long)R * SS;
        out[base + o]          = w;
        out[base + rs + o]     = (1.f - bw) * w;
        out[base + 2 * rs + o] = bw * w;
    }
}

extern "C" void kernel_launch(void* const* d_in, const int* in_sizes, int n_in,
                              void* d_out, int out_size)
{
    const float* pts = (const float*)d_in[0];
    const float* dir = (const float*)d_in[1];
    const float* zv  = (const float*)d_in[2];
    const float* tim = (const float*)d_in[3];

    MLPParams st, dy;
    for (int i = 0; i < 5; i++) {
        st.W[i] = (const float*)d_in[4 + 4 * i];
        st.b[i] = (const float*)d_in[5 + 4 * i];
        dy.W[i] = (const float*)d_in[6 + 4 * i];
        dy.b[i] = (const float*)d_in[7 + 4 * i];
    }

    const int R = in_sizes[2] / SS;

    prepass_kernel<<<2 * NCHUNK * 2, 128>>>(st, dy);

    cudaFuncSetAttribute(nerf_main, cudaFuncAttributeMaxDynamicSharedMemorySize, SM_TOTAL);
    nerf_main<<<R, NTHREADS, SM_TOTAL>>>(pts, dir, zv, tim, st, dy, (float*)d_out, R);
}